// round 3
// baseline (speedup 1.0000x reference)
#include <cuda_runtime.h>

#define BB 8
#define TT 8192
#define DD 512
#define MM 512
#define KIN 544        // DD + 32 fourier dims
#define CH 8           // rows per chunk
#define NC 1024        // TT / CH
#define D4 128         // DD / 4
#define NROWS (BB*MM)  // 4096 output rows

// Scratch (allocation-free rule: __device__ globals)
__device__ float g_chunk[BB * NC * DD];          // 16.8 MB chunk sums
__device__ float g_pref [BB * (NC + 1) * DD];    // 16.8 MB exclusive chunk prefix
__device__ float g_X    [NROWS * KIN];           //  8.9 MB features [4096][544]
__device__ int   g_is64;

// ---------------------------------------------------------------------------
// K0: detect int32 vs int64 beat_bounds layout. Values are in [0, 8192), so
// for int64 every odd 32-bit word of the buffer is zero. We only read the
// first 8192 words (the full buffer if int32; the first half if int64).
// ---------------------------------------------------------------------------
__global__ void k_detect(const unsigned int* __restrict__ bb) {
    __shared__ int s_any;
    if (threadIdx.x == 0) s_any = 0;
    __syncthreads();
    int bad = 0;
    for (int i = 2 * threadIdx.x + 1; i < BB * MM * 2; i += 2 * blockDim.x)
        if (bb[i] != 0u) bad = 1;
    if (bad) atomicOr(&s_any, 1);
    __syncthreads();
    if (threadIdx.x == 0) g_is64 = (s_any == 0) ? 1 : 0;
}

// ---------------------------------------------------------------------------
// K1: per-chunk sums. One block per (b, chunk): 128 threads, each owns one
// float4 column, sums CH=8 rows. Fully coalesced single pass over frame_emb.
// ---------------------------------------------------------------------------
__global__ void k_chunksum(const float4* __restrict__ fr) {
    int b = blockIdx.x >> 10;
    int c = blockIdx.x & (NC - 1);
    const float4* p = fr + (size_t)(b * TT + c * CH) * D4 + threadIdx.x;
    float4 s = make_float4(0.f, 0.f, 0.f, 0.f);
#pragma unroll
    for (int r = 0; r < CH; r++) {
        float4 v = p[(size_t)r * D4];
        s.x += v.x; s.y += v.y; s.z += v.z; s.w += v.w;
    }
    ((float4*)g_chunk)[(size_t)(b * NC + c) * D4 + threadIdx.x] = s;
}

// ---------------------------------------------------------------------------
// K2: exclusive prefix over the 1024 chunks, per (b, float4-column).
// 1024 blocks x 1024 threads; Hillis-Steele scan in 16 KB smem.
// ---------------------------------------------------------------------------
__global__ void k_scan() {
    __shared__ float4 sh[NC];
    int b  = blockIdx.x >> 7;
    int c4 = blockIdx.x & 127;
    int t  = threadIdx.x;
    sh[t] = ((const float4*)g_chunk)[(size_t)(b * NC + t) * D4 + c4];
    __syncthreads();
#pragma unroll
    for (int off = 1; off < NC; off <<= 1) {
        float4 u = make_float4(0.f, 0.f, 0.f, 0.f);
        if (t >= off) u = sh[t - off];
        __syncthreads();
        if (t >= off) {
            float4 w = sh[t];
            w.x += u.x; w.y += u.y; w.z += u.z; w.w += u.w;
            sh[t] = w;
        }
        __syncthreads();
    }
    float4* P = (float4*)g_pref;
    if (t == 0) P[(size_t)(b * (NC + 1)) * D4 + c4] = make_float4(0.f, 0.f, 0.f, 0.f);
    P[(size_t)(b * (NC + 1) + t + 1) * D4 + c4] = sh[t];
}

// ---------------------------------------------------------------------------
// K3: per-segment mean + fourier features -> g_X[4096][544].
// One block per (b, m); seg_sum = P[ce]-P[cs] + tail_e - tail_s where tails
// are <=7 raw rows each. Fourier computed in double to be fast-math-proof.
// ---------------------------------------------------------------------------
__global__ void k_seg(const float4* __restrict__ fr, const void* __restrict__ bbv) {
    int bm = blockIdx.x;
    int b = bm >> 9;
    int m = bm & 511;

    long long s_raw, e_raw;
    if (g_is64) {
        const long long* p = (const long long*)bbv;
        s_raw = p[2 * bm]; e_raw = p[2 * bm + 1];
    } else {
        const int* p = (const int*)bbv;
        s_raw = p[2 * bm]; e_raw = p[2 * bm + 1];
    }
    long long sl = s_raw; if (sl < 0) sl = 0; if (sl > TT - 1) sl = TT - 1;
    long long el = e_raw; if (el > TT) el = TT; if (el < sl + 1) el = sl + 1;
    int s = (int)sl, e = (int)el;
    int cs = s >> 3, ce = e >> 3;

    int t = threadIdx.x;  // 128 float4 columns
    const float4* P = (const float4*)g_pref;
    float4 a = P[(size_t)(b * (NC + 1) + ce) * D4 + t];
    float4 q = P[(size_t)(b * (NC + 1) + cs) * D4 + t];
    a.x -= q.x; a.y -= q.y; a.z -= q.z; a.w -= q.w;

    const float4* fb = fr + (size_t)b * TT * D4 + t;
    for (int r = ce * CH; r < e; r++) {
        float4 v = fb[(size_t)r * D4];
        a.x += v.x; a.y += v.y; a.z += v.z; a.w += v.w;
    }
    for (int r = cs * CH; r < s; r++) {
        float4 v = fb[(size_t)r * D4];
        a.x -= v.x; a.y -= v.y; a.z -= v.z; a.w -= v.w;
    }
    float inv = 1.0f / (float)(e - s);
    a.x *= inv; a.y *= inv; a.z *= inv; a.w *= inv;

    float* X = g_X + (size_t)bm * KIN;
    *(float4*)(X + 4 * t) = a;

    if (t < 8) {
        const float pos = (float)m * (1.0f / 511.0f);
        const float step = (float)(6.907755278982137 / 15.0);  // log(1000)/15 in fp32
        float o[4];
#pragma unroll
        for (int j = 0; j < 4; j++) {
            int i = t * 4 + j;
            int fi = (i < 16) ? i : i - 16;
            float arg = (float)fi * step;
            float freq = (float)exp((double)arg);
            float ang = pos * freq;
            double angd = (double)ang;
            o[j] = (i < 16) ? (float)sin(angd) : (float)cos(angd);
        }
        *(float4*)(X + DD + 4 * t) = make_float4(o[0], o[1], o[2], o[3]);
    }
}

// ---------------------------------------------------------------------------
// K4: out[4096,512] = X[4096,544] @ W[544,512] + b.
// 128x128 block tile, KT=8, 256 threads, 8x8 per-thread micro-tile using
// packed fma.rn.f32x2 (n-dim pairs native from smem 64-bit loads, x broadcast
// packed via mov.b64 {r,r}).
// ---------------------------------------------------------------------------
__global__ void __launch_bounds__(256)
k_gemm(const float* __restrict__ Wt, const float* __restrict__ bias,
       float* __restrict__ out) {
    __shared__ float Xs[8][128];   // [k][m]
    __shared__ float Ws[8][128];   // [k][n]
    int tid = threadIdx.x;
    int tx = tid & 15, ty = tid >> 4;
    int m0 = ty * 8, n0 = tx * 8;
    int rbase = blockIdx.x * 128;
    int cbase = blockIdx.y * 128;

    unsigned long long acc[8][4];
#pragma unroll
    for (int i = 0; i < 8; i++)
#pragma unroll
        for (int j = 0; j < 4; j++) acc[i][j] = 0ull;

    int xrow = tid >> 1;
    int xk = (tid & 1) * 4;
    int wr = tid >> 5;
    int wn = (tid & 31) * 4;

    for (int k0 = 0; k0 < KIN; k0 += 8) {
        float4 xv = *(const float4*)(g_X + (size_t)(rbase + xrow) * KIN + k0 + xk);
        float4 wv = *(const float4*)(Wt + (size_t)(k0 + wr) * DD + cbase + wn);
        Xs[xk + 0][xrow] = xv.x;
        Xs[xk + 1][xrow] = xv.y;
        Xs[xk + 2][xrow] = xv.z;
        Xs[xk + 3][xrow] = xv.w;
        *(float4*)&Ws[wr][wn] = wv;
        __syncthreads();

#pragma unroll
        for (int k = 0; k < 8; k++) {
            float4 a0 = *(const float4*)&Xs[k][m0];
            float4 a1 = *(const float4*)&Xs[k][m0 + 4];
            const unsigned long long* wp = (const unsigned long long*)&Ws[k][n0];
            unsigned long long w0 = wp[0], w1 = wp[1], w2 = wp[2], w3 = wp[3];
            float av[8] = {a0.x, a0.y, a0.z, a0.w, a1.x, a1.y, a1.z, a1.w};
#pragma unroll
            for (int i = 0; i < 8; i++) {
                unsigned long long xx;
                unsigned int ai = __float_as_uint(av[i]);
                asm("mov.b64 %0, {%1, %1};" : "=l"(xx) : "r"(ai));
                asm("fma.rn.f32x2 %0, %1, %2, %0;" : "+l"(acc[i][0]) : "l"(xx), "l"(w0));
                asm("fma.rn.f32x2 %0, %1, %2, %0;" : "+l"(acc[i][1]) : "l"(xx), "l"(w1));
                asm("fma.rn.f32x2 %0, %1, %2, %0;" : "+l"(acc[i][2]) : "l"(xx), "l"(w2));
                asm("fma.rn.f32x2 %0, %1, %2, %0;" : "+l"(acc[i][3]) : "l"(xx), "l"(w3));
            }
        }
        __syncthreads();
    }

    float4 b0 = *(const float4*)(bias + cbase + n0);
    float4 b1 = *(const float4*)(bias + cbase + n0 + 4);
    float bv[8] = {b0.x, b0.y, b0.z, b0.w, b1.x, b1.y, b1.z, b1.w};
#pragma unroll
    for (int i = 0; i < 8; i++) {
        float o[8];
#pragma unroll
        for (int j = 0; j < 4; j++) {
            o[2 * j]     = __uint_as_float((unsigned int)(acc[i][j] & 0xffffffffull)) + bv[2 * j];
            o[2 * j + 1] = __uint_as_float((unsigned int)(acc[i][j] >> 32)) + bv[2 * j + 1];
        }
        float* op = out + (size_t)(rbase + m0 + i) * DD + cbase + n0;
        *(float4*)op       = make_float4(o[0], o[1], o[2], o[3]);
        *(float4*)(op + 4) = make_float4(o[4], o[5], o[6], o[7]);
    }
}

// ---------------------------------------------------------------------------
extern "C" void kernel_launch(void* const* d_in, const int* in_sizes, int n_in,
                              void* d_out, int out_size) {
    const float* frame = (const float*)d_in[0];   // [8, 8192, 512] f32
    const void*  bb    = d_in[1];                 // [8, 512, 2] int32 or int64
    const float* W     = (const float*)d_in[2];   // [544, 512] f32
    const float* bias  = (const float*)d_in[3];   // [512] f32
    float* out = (float*)d_out;                   // [8, 512, 512] f32

    k_detect<<<1, 256>>>((const unsigned int*)bb);
    k_chunksum<<<BB * NC, 128>>>((const float4*)frame);
    k_scan<<<BB * D4, NC>>>();
    k_seg<<<BB * MM, 128>>>((const float4*)frame, bb);
    dim3 g(NROWS / 128, DD / 128);
    k_gemm<<<g, 256>>>(W, bias, out);
}

// round 5
// speedup vs baseline: 1.7880x; 1.7880x over previous
#include <cuda_runtime.h>

#define BB 8
#define TT 8192
#define DD 512
#define MM 512
#define KIN 544        // DD + 32 fourier dims
#define CH 8           // rows per chunk
#define NC 1024        // TT / CH chunks per batch
#define GRP 16         // chunks per group
#define NG 64          // groups per batch (NC / GRP)
#define D4 128         // DD / 4
#define NROWS (BB*MM)  // 4096 output rows

// Scratch (allocation-free rule: __device__ globals)
__device__ float g_cpre[BB * NC * DD];        // 16.8 MB within-group exclusive chunk prefix
__device__ float g_gtot[BB * NG * DD];        //  1.0 MB group totals
__device__ float g_gpre[BB * (NG + 1) * DD];  //  1.1 MB exclusive group prefix
__device__ float g_X   [NROWS * KIN];         //  8.9 MB features [4096][544]
__device__ int   g_is64;

// ---------------------------------------------------------------------------
// K0: detect int32 vs int64 beat_bounds layout (values < 8192, so int64 has
// every odd 32-bit word zero).
// ---------------------------------------------------------------------------
__global__ void k_detect(const unsigned int* __restrict__ bb) {
    __shared__ int s_any;
    if (threadIdx.x == 0) s_any = 0;
    __syncthreads();
    int bad = 0;
    for (int i = 2 * threadIdx.x + 1; i < BB * MM * 2; i += 2 * blockDim.x)
        if (bb[i] != 0u) bad = 1;
    if (bad) atomicOr(&s_any, 1);
    __syncthreads();
    if (threadIdx.x == 0) g_is64 = (s_any == 0) ? 1 : 0;
}

// ---------------------------------------------------------------------------
// K1: fused chunk sums + within-group exclusive prefix + group totals.
// One block per (b, group of 16 chunks = 128 rows). 128 threads = one float4
// column each; all global traffic fully coalesced (2 KB rows). Single pass
// over frame_emb. Replaces the uncoalesced Hillis-Steele scan.
// ---------------------------------------------------------------------------
__global__ void __launch_bounds__(128) k_sumpre(const float4* __restrict__ fr) {
    int b = blockIdx.x >> 6;
    int g = blockIdx.x & (NG - 1);
    int t = threadIdx.x;
    const float4* p = fr + (size_t)(b * TT + g * GRP * CH) * D4 + t;
    float4* cp = (float4*)g_cpre + (size_t)(b * NC + g * GRP) * D4 + t;

    float4 run = make_float4(0.f, 0.f, 0.f, 0.f);
    for (int c = 0; c < GRP; c++) {
        cp[(size_t)c * D4] = run;               // exclusive prefix within group
        float4 s = make_float4(0.f, 0.f, 0.f, 0.f);
#pragma unroll
        for (int r = 0; r < CH; r++) {
            float4 v = p[(size_t)(c * CH + r) * D4];
            s.x += v.x; s.y += v.y; s.z += v.z; s.w += v.w;
        }
        run.x += s.x; run.y += s.y; run.z += s.z; run.w += s.w;
    }
    ((float4*)g_gtot)[(size_t)(b * NG + g) * D4 + t] = run;
}

// ---------------------------------------------------------------------------
// K2: exclusive prefix over 64 group totals per batch. 8 blocks x 128 thr,
// fully coalesced 2 KB rows per iteration. Tiny.
// ---------------------------------------------------------------------------
__global__ void k_gscan() {
    int b = blockIdx.x;
    int t = threadIdx.x;
    const float4* gt = (const float4*)g_gtot + (size_t)b * NG * D4 + t;
    float4* gp = (float4*)g_gpre + (size_t)b * (NG + 1) * D4 + t;
    float4 run = make_float4(0.f, 0.f, 0.f, 0.f);
    for (int g = 0; g < NG; g++) {
        gp[(size_t)g * D4] = run;
        float4 v = gt[(size_t)g * D4];
        run.x += v.x; run.y += v.y; run.z += v.z; run.w += v.w;
    }
    gp[(size_t)NG * D4] = run;
}

// ---------------------------------------------------------------------------
// K3: per-segment mean + fourier features -> g_X[4096][544].
// prefix(c) = g_gpre[c/16] + g_cpre[c]. Tails are FIXED-TRIP unrolled
// predicated loads (7 each side): 18 independent LDGs in flight per thread
// instead of a serial dynamic loop (the round-2 latency bottleneck).
// ---------------------------------------------------------------------------
__global__ void __launch_bounds__(128) k_seg(const float4* __restrict__ fr,
                                             const void* __restrict__ bbv) {
    int bm = blockIdx.x;
    int b = bm >> 9;
    int m = bm & 511;

    long long s_raw, e_raw;
    if (g_is64) {
        const long long* p = (const long long*)bbv;
        s_raw = p[2 * bm]; e_raw = p[2 * bm + 1];
    } else {
        const int* p = (const int*)bbv;
        s_raw = p[2 * bm]; e_raw = p[2 * bm + 1];
    }
    long long sl = s_raw; if (sl < 0) sl = 0; if (sl > TT - 1) sl = TT - 1;
    long long el = e_raw; if (el > TT) el = TT; if (el < sl + 1) el = sl + 1;
    int s = (int)sl, e = (int)el;
    int cs = s >> 3, ce = e >> 3;

    int t = threadIdx.x;  // float4 column
    const float4* CP = (const float4*)g_cpre + (size_t)b * NC * D4 + t;
    const float4* GP = (const float4*)g_gpre + (size_t)b * (NG + 1) * D4 + t;

    float4 a = GP[(size_t)(ce >> 4) * D4];
    float4 q = GP[(size_t)(cs >> 4) * D4];
    {   // cs < NC always; ce == NC only when e == TT (then cpre part is 0)
        float4 c1 = CP[(size_t)cs * D4];
        q.x += c1.x; q.y += c1.y; q.z += c1.z; q.w += c1.w;
        if (ce < NC) {
            float4 c2 = CP[(size_t)ce * D4];
            a.x += c2.x; a.y += c2.y; a.z += c2.z; a.w += c2.w;
        }
    }
    a.x -= q.x; a.y -= q.y; a.z -= q.z; a.w -= q.w;

    const float4* fb = fr + (size_t)b * TT * D4 + t;
    float4 ve[7], vs[7];
#pragma unroll
    for (int j = 0; j < 7; j++) {
        int r = ce * CH + j;
        ve[j] = make_float4(0.f, 0.f, 0.f, 0.f);
        if (r < e) ve[j] = fb[(size_t)r * D4];
    }
#pragma unroll
    for (int j = 0; j < 7; j++) {
        int r = cs * CH + j;
        vs[j] = make_float4(0.f, 0.f, 0.f, 0.f);
        if (r < s) vs[j] = fb[(size_t)r * D4];
    }
#pragma unroll
    for (int j = 0; j < 7; j++) {
        a.x += ve[j].x - vs[j].x;
        a.y += ve[j].y - vs[j].y;
        a.z += ve[j].z - vs[j].z;
        a.w += ve[j].w - vs[j].w;
    }
    float inv = 1.0f / (float)(e - s);
    a.x *= inv; a.y *= inv; a.z *= inv; a.w *= inv;

    float* X = g_X + (size_t)bm * KIN;
    *(float4*)(X + 4 * t) = a;

    if (t < 8) {
        const float pos = (float)m * (1.0f / 511.0f);
        const float step = (float)(6.907755278982137 / 15.0);  // log(1000)/15
        float o[4];
#pragma unroll
        for (int j = 0; j < 4; j++) {
            int i = t * 4 + j;
            int fi = (i < 16) ? i : i - 16;
            float arg = (float)fi * step;
            float freq = (float)exp((double)arg);
            float ang = pos * freq;
            double angd = (double)ang;
            o[j] = (i < 16) ? (float)sin(angd) : (float)cos(angd);
        }
        *(float4*)(X + DD + 4 * t) = make_float4(o[0], o[1], o[2], o[3]);
    }
}

// ---------------------------------------------------------------------------
// K4: out[4096,512] = X[4096,544] @ W[544,512] + b.
// 128x128 block tile, KT=8, 256 threads, 8x8 micro-tile with packed
// fma.rn.f32x2. Double-buffered smem (reg prefetch, one sync per k-tile).
// ---------------------------------------------------------------------------
__global__ void __launch_bounds__(256)
k_gemm(const float* __restrict__ Wt, const float* __restrict__ bias,
       float* __restrict__ out) {
    __shared__ float Xs[2][8][128];   // [buf][k][m]
    __shared__ float Ws[2][8][128];   // [buf][k][n]
    int tid = threadIdx.x;
    int tx = tid & 15, ty = tid >> 4;
    int m0 = ty * 8, n0 = tx * 8;
    int rbase = blockIdx.x * 128;
    int cbase = blockIdx.y * 128;

    unsigned long long acc[8][4];
#pragma unroll
    for (int i = 0; i < 8; i++)
#pragma unroll
        for (int j = 0; j < 4; j++) acc[i][j] = 0ull;

    int xrow = tid >> 1;
    int xk = (tid & 1) * 4;
    int wr = tid >> 5;
    int wn = (tid & 31) * 4;
    const float* Xg = g_X + (size_t)(rbase + xrow) * KIN + xk;
    const float* Wg = Wt + (size_t)wr * DD + cbase + wn;

    float4 xv = *(const float4*)Xg;
    float4 wv = *(const float4*)Wg;
    Xs[0][xk + 0][xrow] = xv.x;
    Xs[0][xk + 1][xrow] = xv.y;
    Xs[0][xk + 2][xrow] = xv.z;
    Xs[0][xk + 3][xrow] = xv.w;
    *(float4*)&Ws[0][wr][wn] = wv;
    __syncthreads();

    const int NT = KIN / 8;  // 68 k-tiles
    for (int ti = 0; ti < NT; ti++) {
        int cb = ti & 1;
        if (ti + 1 < NT) {
            xv = *(const float4*)(Xg + (ti + 1) * 8);
            wv = *(const float4*)(Wg + (size_t)(ti + 1) * 8 * DD);
        }
#pragma unroll
        for (int k = 0; k < 8; k++) {
            float4 a0 = *(const float4*)&Xs[cb][k][m0];
            float4 a1 = *(const float4*)&Xs[cb][k][m0 + 4];
            const unsigned long long* wp = (const unsigned long long*)&Ws[cb][k][n0];
            unsigned long long w0 = wp[0], w1 = wp[1], w2 = wp[2], w3 = wp[3];
            float av[8] = {a0.x, a0.y, a0.z, a0.w, a1.x, a1.y, a1.z, a1.w};
#pragma unroll
            for (int i = 0; i < 8; i++) {
                unsigned long long xx;
                unsigned int ai = __float_as_uint(av[i]);
                asm("mov.b64 %0, {%1, %1};" : "=l"(xx) : "r"(ai));
                asm("fma.rn.f32x2 %0, %1, %2, %0;" : "+l"(acc[i][0]) : "l"(xx), "l"(w0));
                asm("fma.rn.f32x2 %0, %1, %2, %0;" : "+l"(acc[i][1]) : "l"(xx), "l"(w1));
                asm("fma.rn.f32x2 %0, %1, %2, %0;" : "+l"(acc[i][2]) : "l"(xx), "l"(w2));
                asm("fma.rn.f32x2 %0, %1, %2, %0;" : "+l"(acc[i][3]) : "l"(xx), "l"(w3));
            }
        }
        if (ti + 1 < NT) {
            int nb = cb ^ 1;
            Xs[nb][xk + 0][xrow] = xv.x;
            Xs[nb][xk + 1][xrow] = xv.y;
            Xs[nb][xk + 2][xrow] = xv.z;
            Xs[nb][xk + 3][xrow] = xv.w;
            *(float4*)&Ws[nb][wr][wn] = wv;
        }
        __syncthreads();
    }

    float4 b0 = *(const float4*)(bias + cbase + n0);
    float4 b1 = *(const float4*)(bias + cbase + n0 + 4);
    float bv[8] = {b0.x, b0.y, b0.z, b0.w, b1.x, b1.y, b1.z, b1.w};
#pragma unroll
    for (int i = 0; i < 8; i++) {
        float o[8];
#pragma unroll
        for (int j = 0; j < 4; j++) {
            o[2 * j]     = __uint_as_float((unsigned int)(acc[i][j] & 0xffffffffull)) + bv[2 * j];
            o[2 * j + 1] = __uint_as_float((unsigned int)(acc[i][j] >> 32)) + bv[2 * j + 1];
        }
        float* op = out + (size_t)(rbase + m0 + i) * DD + cbase + n0;
        *(float4*)op       = make_float4(o[0], o[1], o[2], o[3]);
        *(float4*)(op + 4) = make_float4(o[4], o[5], o[6], o[7]);
    }
}

// ---------------------------------------------------------------------------
extern "C" void kernel_launch(void* const* d_in, const int* in_sizes, int n_in,
                              void* d_out, int out_size) {
    const float* frame = (const float*)d_in[0];   // [8, 8192, 512] f32
    const void*  bb    = d_in[1];                 // [8, 512, 2] int32 or int64
    const float* W     = (const float*)d_in[2];   // [544, 512] f32
    const float* bias  = (const float*)d_in[3];   // [512] f32
    float* out = (float*)d_out;                   // [8, 512, 512] f32

    k_detect<<<1, 256>>>((const unsigned int*)bb);
    k_sumpre<<<BB * NG, 128>>>((const float4*)frame);
    k_gscan<<<BB, 128>>>();
    k_seg<<<BB * MM, 128>>>((const float4*)frame, bb);
    dim3 g(NROWS / 128, DD / 128);
    k_gemm<<<g, 256>>>(W, bias, out);
}

// round 6
// speedup vs baseline: 2.3132x; 1.2937x over previous
#include <cuda_runtime.h>

#define BB 8
#define TT 8192
#define DD 512
#define MM 512
#define KIN 544        // DD + 32 fourier dims
#define CH 8           // rows per chunk
#define NC 1024        // TT / CH chunks per batch
#define GRP 8          // chunks per group
#define NG 128         // groups per batch (NC / GRP)
#define D4 128         // DD / 4
#define NROWS (BB*MM)  // 4096 output rows

// Scratch (allocation-free rule: __device__ globals)
__device__ float g_cpre[BB * NC * DD];        // 16.8 MB within-group exclusive chunk prefix
__device__ float g_gtot[BB * NG * DD];        //  2.1 MB group totals
__device__ float g_gpre[BB * (NG + 1) * DD];  //  2.1 MB exclusive group prefix
__device__ float g_X   [NROWS * KIN];         //  8.9 MB features [4096][544]
__device__ int2  g_se  [NROWS];               // clamped (s, e) per segment
__device__ int   g_is64;

// ---------------------------------------------------------------------------
// K0: detect int32 vs int64 beat_bounds layout (values < 8192, so int64 has
// every odd 32-bit word zero).
// ---------------------------------------------------------------------------
__global__ void k_detect(const unsigned int* __restrict__ bb) {
    __shared__ int s_any;
    if (threadIdx.x == 0) s_any = 0;
    __syncthreads();
    int bad = 0;
    for (int i = 2 * threadIdx.x + 1; i < BB * MM * 2; i += 2 * blockDim.x)
        if (bb[i] != 0u) bad = 1;
    if (bad) atomicOr(&s_any, 1);
    __syncthreads();
    if (threadIdx.x == 0) g_is64 = (s_any == 0) ? 1 : 0;
}

// ---------------------------------------------------------------------------
// K0b: clamp bounds once into g_se (removes int64 branch + clamp chain from
// the hot pooling kernel).
// ---------------------------------------------------------------------------
__global__ void k_bounds(const void* __restrict__ bbv) {
    int bm = blockIdx.x * blockDim.x + threadIdx.x;
    if (bm >= NROWS) return;
    long long s_raw, e_raw;
    if (g_is64) {
        const long long* p = (const long long*)bbv;
        s_raw = p[2 * bm]; e_raw = p[2 * bm + 1];
    } else {
        const int* p = (const int*)bbv;
        s_raw = p[2 * bm]; e_raw = p[2 * bm + 1];
    }
    long long sl = s_raw; if (sl < 0) sl = 0; if (sl > TT - 1) sl = TT - 1;
    long long el = e_raw; if (el > TT) el = TT; if (el < sl + 1) el = sl + 1;
    g_se[bm] = make_int2((int)sl, (int)el);
}

// ---------------------------------------------------------------------------
// K0c: fourier features, computed ONCE per (m, i) with the DP math spread
// across 16K threads, broadcast to all 8 batches. Was previously recomputed
// per-block inside k_seg, serializing every block on the FP64 pipe.
// ---------------------------------------------------------------------------
__global__ void k_four() {
    int m = blockIdx.x;       // 0..511
    int i = threadIdx.x;      // 0..31
    const float pos = (float)m * (1.0f / 511.0f);
    const float step = (float)(6.907755278982137 / 15.0);  // log(1000)/15
    int fi = (i < 16) ? i : i - 16;
    float arg = (float)fi * step;
    float freq = (float)exp((double)arg);
    float ang = pos * freq;                 // fp32 angle, matching reference
    double angd = (double)ang;
    float v = (i < 16) ? (float)sin(angd) : (float)cos(angd);
#pragma unroll
    for (int b = 0; b < BB; b++)
        g_X[(size_t)(b * MM + m) * KIN + DD + i] = v;
}

// ---------------------------------------------------------------------------
// K1: fused chunk sums + within-group exclusive prefix + group totals.
// One block per (b, group of 8 chunks = 64 rows). 128 threads = one float4
// column each; all global traffic fully coalesced (2 KB rows). 1024 blocks
// (~7/SM resident) for latency hiding on the streaming pass.
// ---------------------------------------------------------------------------
__global__ void __launch_bounds__(128) k_sumpre(const float4* __restrict__ fr) {
    int b = blockIdx.x >> 7;
    int g = blockIdx.x & (NG - 1);
    int t = threadIdx.x;
    const float4* p = fr + (size_t)(b * TT + g * GRP * CH) * D4 + t;
    float4* cp = (float4*)g_cpre + (size_t)(b * NC + g * GRP) * D4 + t;

    float4 run = make_float4(0.f, 0.f, 0.f, 0.f);
#pragma unroll
    for (int c = 0; c < GRP; c++) {
        cp[(size_t)c * D4] = run;               // exclusive prefix within group
        float4 s = make_float4(0.f, 0.f, 0.f, 0.f);
#pragma unroll
        for (int r = 0; r < CH; r++) {
            float4 v = p[(size_t)(c * CH + r) * D4];
            s.x += v.x; s.y += v.y; s.z += v.z; s.w += v.w;
        }
        run.x += s.x; run.y += s.y; run.z += s.z; run.w += s.w;
    }
    ((float4*)g_gtot)[(size_t)(b * NG + g) * D4 + t] = run;
}

// ---------------------------------------------------------------------------
// K2: exclusive prefix over 128 group totals per batch. 8 blocks x 128 thr,
// fully coalesced 2 KB rows per iteration. Tiny.
// ---------------------------------------------------------------------------
__global__ void k_gscan() {
    int b = blockIdx.x;
    int t = threadIdx.x;
    const float4* gt = (const float4*)g_gtot + (size_t)b * NG * D4 + t;
    float4* gp = (float4*)g_gpre + (size_t)b * (NG + 1) * D4 + t;
    float4 run = make_float4(0.f, 0.f, 0.f, 0.f);
    for (int g = 0; g < NG; g++) {
        gp[(size_t)g * D4] = run;
        float4 v = gt[(size_t)g * D4];
        run.x += v.x; run.y += v.y; run.z += v.z; run.w += v.w;
    }
    gp[(size_t)NG * D4] = run;
}

// ---------------------------------------------------------------------------
// K3: per-segment mean -> g_X[:, 0:512]. prefix(c) = g_gpre[c/8] + g_cpre[c].
// Tails are fixed-trip unrolled predicated loads (7 each side) = 18
// independent LDGs in flight per thread. No DP, no fourier, no clamp chain:
// head is a single 8 B L2-hot load of g_se.
// ---------------------------------------------------------------------------
__global__ void __launch_bounds__(128) k_seg(const float4* __restrict__ fr) {
    int bm = blockIdx.x;
    int b = bm >> 9;

    int2 se = g_se[bm];
    int s = se.x, e = se.y;
    int cs = s >> 3, ce = e >> 3;

    int t = threadIdx.x;  // float4 column
    const float4* CP = (const float4*)g_cpre + (size_t)b * NC * D4 + t;
    const float4* GP = (const float4*)g_gpre + (size_t)b * (NG + 1) * D4 + t;

    float4 a = GP[(size_t)(ce >> 3) * D4];
    float4 q = GP[(size_t)(cs >> 3) * D4];
    {   // cs < NC always; ce == NC only when e == TT (then cpre part is 0)
        float4 c1 = CP[(size_t)cs * D4];
        q.x += c1.x; q.y += c1.y; q.z += c1.z; q.w += c1.w;
        if (ce < NC) {
            float4 c2 = CP[(size_t)ce * D4];
            a.x += c2.x; a.y += c2.y; a.z += c2.z; a.w += c2.w;
        }
    }
    a.x -= q.x; a.y -= q.y; a.z -= q.z; a.w -= q.w;

    const float4* fb = fr + (size_t)b * TT * D4 + t;
    float4 ve[7], vs[7];
#pragma unroll
    for (int j = 0; j < 7; j++) {
        int r = ce * CH + j;
        ve[j] = make_float4(0.f, 0.f, 0.f, 0.f);
        if (r < e) ve[j] = fb[(size_t)r * D4];
    }
#pragma unroll
    for (int j = 0; j < 7; j++) {
        int r = cs * CH + j;
        vs[j] = make_float4(0.f, 0.f, 0.f, 0.f);
        if (r < s) vs[j] = fb[(size_t)r * D4];
    }
#pragma unroll
    for (int j = 0; j < 7; j++) {
        a.x += ve[j].x - vs[j].x;
        a.y += ve[j].y - vs[j].y;
        a.z += ve[j].z - vs[j].z;
        a.w += ve[j].w - vs[j].w;
    }
    float inv = 1.0f / (float)(e - s);
    a.x *= inv; a.y *= inv; a.z *= inv; a.w *= inv;

    *(float4*)(g_X + (size_t)bm * KIN + 4 * t) = a;
}

// ---------------------------------------------------------------------------
// K4: out[4096,512] = X[4096,544] @ W[544,512] + b.
// 128x128 block tile, KT=8, 256 threads, 8x8 micro-tile with packed
// fma.rn.f32x2. Double-buffered smem (reg prefetch, one sync per k-tile).
// ---------------------------------------------------------------------------
__global__ void __launch_bounds__(256)
k_gemm(const float* __restrict__ Wt, const float* __restrict__ bias,
       float* __restrict__ out) {
    __shared__ float Xs[2][8][128];   // [buf][k][m]
    __shared__ float Ws[2][8][128];   // [buf][k][n]
    int tid = threadIdx.x;
    int tx = tid & 15, ty = tid >> 4;
    int m0 = ty * 8, n0 = tx * 8;
    int rbase = blockIdx.x * 128;
    int cbase = blockIdx.y * 128;

    unsigned long long acc[8][4];
#pragma unroll
    for (int i = 0; i < 8; i++)
#pragma unroll
        for (int j = 0; j < 4; j++) acc[i][j] = 0ull;

    int xrow = tid >> 1;
    int xk = (tid & 1) * 4;
    int wr = tid >> 5;
    int wn = (tid & 31) * 4;
    const float* Xg = g_X + (size_t)(rbase + xrow) * KIN + xk;
    const float* Wg = Wt + (size_t)wr * DD + cbase + wn;

    float4 xv = *(const float4*)Xg;
    float4 wv = *(const float4*)Wg;
    Xs[0][xk + 0][xrow] = xv.x;
    Xs[0][xk + 1][xrow] = xv.y;
    Xs[0][xk + 2][xrow] = xv.z;
    Xs[0][xk + 3][xrow] = xv.w;
    *(float4*)&Ws[0][wr][wn] = wv;
    __syncthreads();

    const int NT = KIN / 8;  // 68 k-tiles
    for (int ti = 0; ti < NT; ti++) {
        int cb = ti & 1;
        if (ti + 1 < NT) {
            xv = *(const float4*)(Xg + (ti + 1) * 8);
            wv = *(const float4*)(Wg + (size_t)(ti + 1) * 8 * DD);
        }
#pragma unroll
        for (int k = 0; k < 8; k++) {
            float4 a0 = *(const float4*)&Xs[cb][k][m0];
            float4 a1 = *(const float4*)&Xs[cb][k][m0 + 4];
            const unsigned long long* wp = (const unsigned long long*)&Ws[cb][k][n0];
            unsigned long long w0 = wp[0], w1 = wp[1], w2 = wp[2], w3 = wp[3];
            float av[8] = {a0.x, a0.y, a0.z, a0.w, a1.x, a1.y, a1.z, a1.w};
#pragma unroll
            for (int i = 0; i < 8; i++) {
                unsigned long long xx;
                unsigned int ai = __float_as_uint(av[i]);
                asm("mov.b64 %0, {%1, %1};" : "=l"(xx) : "r"(ai));
                asm("fma.rn.f32x2 %0, %1, %2, %0;" : "+l"(acc[i][0]) : "l"(xx), "l"(w0));
                asm("fma.rn.f32x2 %0, %1, %2, %0;" : "+l"(acc[i][1]) : "l"(xx), "l"(w1));
                asm("fma.rn.f32x2 %0, %1, %2, %0;" : "+l"(acc[i][2]) : "l"(xx), "l"(w2));
                asm("fma.rn.f32x2 %0, %1, %2, %0;" : "+l"(acc[i][3]) : "l"(xx), "l"(w3));
            }
        }
        if (ti + 1 < NT) {
            int nb = cb ^ 1;
            Xs[nb][xk + 0][xrow] = xv.x;
            Xs[nb][xk + 1][xrow] = xv.y;
            Xs[nb][xk + 2][xrow] = xv.z;
            Xs[nb][xk + 3][xrow] = xv.w;
            *(float4*)&Ws[nb][wr][wn] = wv;
        }
        __syncthreads();
    }

    float4 b0 = *(const float4*)(bias + cbase + n0);
    float4 b1 = *(const float4*)(bias + cbase + n0 + 4);
    float bv[8] = {b0.x, b0.y, b0.z, b0.w, b1.x, b1.y, b1.z, b1.w};
#pragma unroll
    for (int i = 0; i < 8; i++) {
        float o[8];
#pragma unroll
        for (int j = 0; j < 4; j++) {
            o[2 * j]     = __uint_as_float((unsigned int)(acc[i][j] & 0xffffffffull)) + bv[2 * j];
            o[2 * j + 1] = __uint_as_float((unsigned int)(acc[i][j] >> 32)) + bv[2 * j + 1];
        }
        float* op = out + (size_t)(rbase + m0 + i) * DD + cbase + n0;
        *(float4*)op       = make_float4(o[0], o[1], o[2], o[3]);
        *(float4*)(op + 4) = make_float4(o[4], o[5], o[6], o[7]);
    }
}

// ---------------------------------------------------------------------------
extern "C" void kernel_launch(void* const* d_in, const int* in_sizes, int n_in,
                              void* d_out, int out_size) {
    const float* frame = (const float*)d_in[0];   // [8, 8192, 512] f32
    const void*  bb    = d_in[1];                 // [8, 512, 2] int32 or int64
    const float* W     = (const float*)d_in[2];   // [544, 512] f32
    const float* bias  = (const float*)d_in[3];   // [512] f32
    float* out = (float*)d_out;                   // [8, 512, 512] f32

    k_detect<<<1, 256>>>((const unsigned int*)bb);
    k_bounds<<<16, 256>>>(bb);
    k_four<<<MM, 32>>>();
    k_sumpre<<<BB * NG, 128>>>((const float4*)frame);
    k_gscan<<<BB, 128>>>();
    k_seg<<<BB * MM, 128>>>((const float4*)frame);
    dim3 g(NROWS / 128, DD / 128);
    k_gemm<<<g, 256>>>(W, bias, out);
}

// round 8
// speedup vs baseline: 2.6822x; 1.1595x over previous
#include <cuda_runtime.h>

#define BB 8
#define TT 8192
#define DD 512
#define MM 512
#define KIN 544        // DD + 32 fourier dims
#define CH 8           // rows per chunk
#define NC 1024        // TT / CH chunks per batch
#define GRP 8          // chunks per group
#define NG 128         // groups per batch (NC / GRP)
#define D4 128         // DD / 4
#define NROWS (BB*MM)  // 4096 output rows

// Scratch (allocation-free rule: __device__ globals)
__device__ float g_cpre[BB * NC * DD];        // 16.8 MB within-group exclusive chunk prefix
__device__ float g_gtot[BB * NG * DD];        //  2.1 MB group totals
__device__ float g_gpre[BB * (NG + 1) * DD];  //  2.1 MB exclusive group prefix
__device__ float g_X   [NROWS * KIN];         //  8.9 MB features [4096][544]
__device__ int2  g_se  [NROWS];               // clamped (s, e) per segment
__device__ int   g_is64;

// ---------------------------------------------------------------------------
// K0: detect int32 vs int64 beat_bounds layout (values < 8192, so int64 has
// every odd 32-bit word zero).
// ---------------------------------------------------------------------------
__global__ void k_detect(const unsigned int* __restrict__ bb) {
    __shared__ int s_any;
    if (threadIdx.x == 0) s_any = 0;
    __syncthreads();
    int bad = 0;
    for (int i = 2 * threadIdx.x + 1; i < BB * MM * 2; i += 2 * blockDim.x)
        if (bb[i] != 0u) bad = 1;
    if (bad) atomicOr(&s_any, 1);
    __syncthreads();
    if (threadIdx.x == 0) g_is64 = (s_any == 0) ? 1 : 0;
}

// ---------------------------------------------------------------------------
// K0b: clamp bounds once into g_se.
// ---------------------------------------------------------------------------
__global__ void k_bounds(const void* __restrict__ bbv) {
    int bm = blockIdx.x * blockDim.x + threadIdx.x;
    if (bm >= NROWS) return;
    long long s_raw, e_raw;
    if (g_is64) {
        const long long* p = (const long long*)bbv;
        s_raw = p[2 * bm]; e_raw = p[2 * bm + 1];
    } else {
        const int* p = (const int*)bbv;
        s_raw = p[2 * bm]; e_raw = p[2 * bm + 1];
    }
    long long sl = s_raw; if (sl < 0) sl = 0; if (sl > TT - 1) sl = TT - 1;
    long long el = e_raw; if (el > TT) el = TT; if (el < sl + 1) el = sl + 1;
    g_se[bm] = make_int2((int)sl, (int)el);
}

// ---------------------------------------------------------------------------
// K0c: fourier features, computed once per (m, i), DP spread chip-wide,
// broadcast to all 8 batches.
// ---------------------------------------------------------------------------
__global__ void k_four() {
    int m = blockIdx.x;       // 0..511
    int i = threadIdx.x;      // 0..31
    const float pos = (float)m * (1.0f / 511.0f);
    const float step = (float)(6.907755278982137 / 15.0);  // log(1000)/15
    int fi = (i < 16) ? i : i - 16;
    float arg = (float)fi * step;
    float freq = (float)exp((double)arg);
    float ang = pos * freq;
    double angd = (double)ang;
    float v = (i < 16) ? (float)sin(angd) : (float)cos(angd);
#pragma unroll
    for (int b = 0; b < BB; b++)
        g_X[(size_t)(b * MM + m) * KIN + DD + i] = v;
}

// ---------------------------------------------------------------------------
// K1: fused chunk sums + within-group exclusive prefix + group totals.
// One block per (b, group of 8 chunks = 64 rows), fully coalesced; near its
// DRAM floor (69.9% per round-6 ncu).
// ---------------------------------------------------------------------------
__global__ void __launch_bounds__(128) k_sumpre(const float4* __restrict__ fr) {
    int b = blockIdx.x >> 7;
    int g = blockIdx.x & (NG - 1);
    int t = threadIdx.x;
    const float4* p = fr + (size_t)(b * TT + g * GRP * CH) * D4 + t;
    float4* cp = (float4*)g_cpre + (size_t)(b * NC + g * GRP) * D4 + t;

    float4 run = make_float4(0.f, 0.f, 0.f, 0.f);
#pragma unroll
    for (int c = 0; c < GRP; c++) {
        cp[(size_t)c * D4] = run;
        float4 s = make_float4(0.f, 0.f, 0.f, 0.f);
#pragma unroll
        for (int r = 0; r < CH; r++) {
            float4 v = p[(size_t)(c * CH + r) * D4];
            s.x += v.x; s.y += v.y; s.z += v.z; s.w += v.w;
        }
        run.x += s.x; run.y += s.y; run.z += s.z; run.w += s.w;
    }
    ((float4*)g_gtot)[(size_t)(b * NG + g) * D4 + t] = run;
}

// ---------------------------------------------------------------------------
// K2: exclusive prefix over 128 group totals, WARP-PARALLEL. One warp per
// (batch, float4-column) = 1024 warps; each lane owns 4 consecutive groups,
// shfl exclusive scan across lanes. Replaces the 8-block serial loop
// (~128 dependent L2 round trips) that cost ~15 us.
// ---------------------------------------------------------------------------
__global__ void __launch_bounds__(256) k_gscan() {
    int wid = threadIdx.x >> 5, l = threadIdx.x & 31;
    int b  = blockIdx.x >> 4;
    int c4 = (blockIdx.x & 15) * 8 + wid;
    const float4* gt = (const float4*)g_gtot + (size_t)b * NG * D4 + c4;
    float4* gp = (float4*)g_gpre + (size_t)b * (NG + 1) * D4 + c4;

    float4 v[4];
    float4 s = make_float4(0.f, 0.f, 0.f, 0.f);
#pragma unroll
    for (int j = 0; j < 4; j++) {
        v[j] = gt[(size_t)(4 * l + j) * D4];
        s.x += v[j].x; s.y += v[j].y; s.z += v[j].z; s.w += v[j].w;
    }
    // inclusive warp scan of s, then convert to exclusive
    float4 inc = s;
#pragma unroll
    for (int off = 1; off < 32; off <<= 1) {
        float ux = __shfl_up_sync(0xffffffffu, inc.x, off);
        float uy = __shfl_up_sync(0xffffffffu, inc.y, off);
        float uz = __shfl_up_sync(0xffffffffu, inc.z, off);
        float uw = __shfl_up_sync(0xffffffffu, inc.w, off);
        if (l >= off) { inc.x += ux; inc.y += uy; inc.z += uz; inc.w += uw; }
    }
    float4 run = make_float4(inc.x - s.x, inc.y - s.y, inc.z - s.z, inc.w - s.w);
#pragma unroll
    for (int j = 0; j < 4; j++) {
        gp[(size_t)(4 * l + j) * D4] = run;
        run.x += v[j].x; run.y += v[j].y; run.z += v[j].z; run.w += v[j].w;
    }
    if (l == 31) gp[(size_t)NG * D4] = run;
}

// ---------------------------------------------------------------------------
// K3: per-segment mean -> g_X[:, 0:512]. Fixed-trip predicated tails, 18
// independent LDGs in flight; head is one 8 B L2-hot load.
// ---------------------------------------------------------------------------
__global__ void __launch_bounds__(128) k_seg(const float4* __restrict__ fr) {
    int bm = blockIdx.x;
    int b = bm >> 9;

    int2 se = g_se[bm];
    int s = se.x, e = se.y;
    int cs = s >> 3, ce = e >> 3;

    int t = threadIdx.x;  // float4 column
    const float4* CP = (const float4*)g_cpre + (size_t)b * NC * D4 + t;
    const float4* GP = (const float4*)g_gpre + (size_t)b * (NG + 1) * D4 + t;

    float4 a = GP[(size_t)(ce >> 3) * D4];
    float4 q = GP[(size_t)(cs >> 3) * D4];
    {
        float4 c1 = CP[(size_t)cs * D4];
        q.x += c1.x; q.y += c1.y; q.z += c1.z; q.w += c1.w;
        if (ce < NC) {
            float4 c2 = CP[(size_t)ce * D4];
            a.x += c2.x; a.y += c2.y; a.z += c2.z; a.w += c2.w;
        }
    }
    a.x -= q.x; a.y -= q.y; a.z -= q.z; a.w -= q.w;

    const float4* fb = fr + (size_t)b * TT * D4 + t;
    float4 ve[7], vs[7];
#pragma unroll
    for (int j = 0; j < 7; j++) {
        int r = ce * CH + j;
        ve[j] = make_float4(0.f, 0.f, 0.f, 0.f);
        if (r < e) ve[j] = fb[(size_t)r * D4];
    }
#pragma unroll
    for (int j = 0; j < 7; j++) {
        int r = cs * CH + j;
        vs[j] = make_float4(0.f, 0.f, 0.f, 0.f);
        if (r < s) vs[j] = fb[(size_t)r * D4];
    }
#pragma unroll
    for (int j = 0; j < 7; j++) {
        a.x += ve[j].x - vs[j].x;
        a.y += ve[j].y - vs[j].y;
        a.z += ve[j].z - vs[j].z;
        a.w += ve[j].w - vs[j].w;
    }
    float inv = 1.0f / (float)(e - s);
    a.x *= inv; a.y *= inv; a.z *= inv; a.w *= inv;

    *(float4*)(g_X + (size_t)bm * KIN + 4 * t) = a;
}

// ---------------------------------------------------------------------------
// K4: out[4096,512] = X[4096,544] @ W[544,512] + b.
// 128x128 tile, 256 threads, 8x8 micro-tile of packed fma.rn.f32x2.
// X tile stored DUPLICATED in smem (Xs[k][2m]=Xs[k][2m+1]=x) so the {x,x}
// broadcast operand is a single conflict-free LDS.64 — no mov.b64 dups in
// the inner loop. n micro-tile split into two stride-16B groups so W LDS.128
// is conflict-free. 42 issue slots per 32 FFMA2 (was ~54).
// ---------------------------------------------------------------------------
__global__ void __launch_bounds__(256)
k_gemm(const float* __restrict__ Wt, const float* __restrict__ bias,
       float* __restrict__ out) {
    __shared__ float Xs[2][8][256];   // [buf][k][2*m] duplicated
    __shared__ float Ws[2][8][128];   // [buf][k][n]
    int tid = threadIdx.x;
    int tx = tid & 15, ty = tid >> 4;
    int rbase = blockIdx.x * 128;
    int cbase = blockIdx.y * 128;

    unsigned long long acc[8][4];
#pragma unroll
    for (int i = 0; i < 8; i++)
#pragma unroll
        for (int j = 0; j < 4; j++) acc[i][j] = 0ull;

    int xrow = tid >> 1;
    int xk = (tid & 1) * 4;
    int wr = tid >> 5;
    int wn = (tid & 31) * 4;
    const float* Xg = g_X + (size_t)(rbase + xrow) * KIN + xk;
    const float* Wg = Wt + (size_t)wr * DD + cbase + wn;

    float4 xv = *(const float4*)Xg;
    float4 wv = *(const float4*)Wg;
    {
        float xa[4] = {xv.x, xv.y, xv.z, xv.w};
#pragma unroll
        for (int j = 0; j < 4; j++)
            *(float2*)&Xs[0][xk + j][2 * xrow] = make_float2(xa[j], xa[j]);
    }
    *(float4*)&Ws[0][wr][wn] = wv;
    __syncthreads();

    const int NT = KIN / 8;  // 68 k-tiles
    for (int ti = 0; ti < NT; ti++) {
        int cb = ti & 1;
        if (ti + 1 < NT) {
            xv = *(const float4*)(Xg + (ti + 1) * 8);
            wv = *(const float4*)(Wg + (size_t)(ti + 1) * 8 * DD);
        }
#pragma unroll
        for (int k = 0; k < 8; k++) {
            const unsigned long long* ap = (const unsigned long long*)&Xs[cb][k][0];
            const unsigned long long* wp = (const unsigned long long*)&Ws[cb][k][0];
            unsigned long long w0 = wp[2 * tx];
            unsigned long long w1 = wp[2 * tx + 1];
            unsigned long long w2 = wp[32 + 2 * tx];
            unsigned long long w3 = wp[32 + 2 * tx + 1];
#pragma unroll
            for (int i = 0; i < 8; i++) {
                int mi = (i < 4) ? (ty * 4 + i) : (64 + ty * 4 + i - 4);
                unsigned long long xx = ap[mi];   // {x, x} via one LDS.64
                asm("fma.rn.f32x2 %0, %1, %2, %0;" : "+l"(acc[i][0]) : "l"(xx), "l"(w0));
                asm("fma.rn.f32x2 %0, %1, %2, %0;" : "+l"(acc[i][1]) : "l"(xx), "l"(w1));
                asm("fma.rn.f32x2 %0, %1, %2, %0;" : "+l"(acc[i][2]) : "l"(xx), "l"(w2));
                asm("fma.rn.f32x2 %0, %1, %2, %0;" : "+l"(acc[i][3]) : "l"(xx), "l"(w3));
            }
        }
        if (ti + 1 < NT) {
            int nb = cb ^ 1;
            float xa[4] = {xv.x, xv.y, xv.z, xv.w};
#pragma unroll
            for (int j = 0; j < 4; j++)
                *(float2*)&Xs[nb][xk + j][2 * xrow] = make_float2(xa[j], xa[j]);
            *(float4*)&Ws[nb][wr][wn] = wv;
        }
        __syncthreads();
    }

    // epilogue: n groups at cbase+tx*4 and cbase+64+tx*4
    float4 bA = *(const float4*)(bias + cbase + tx * 4);
    float4 bBv = *(const float4*)(bias + cbase + 64 + tx * 4);
#pragma unroll
    for (int i = 0; i < 8; i++) {
        int mrow = rbase + ((i < 4) ? (ty * 4 + i) : (64 + ty * 4 + i - 4));
        float4 oA = make_float4(
            __uint_as_float((unsigned int)(acc[i][0] & 0xffffffffull)) + bA.x,
            __uint_as_float((unsigned int)(acc[i][0] >> 32)) + bA.y,
            __uint_as_float((unsigned int)(acc[i][1] & 0xffffffffull)) + bA.z,
            __uint_as_float((unsigned int)(acc[i][1] >> 32)) + bA.w);
        float4 oB = make_float4(
            __uint_as_float((unsigned int)(acc[i][2] & 0xffffffffull)) + bBv.x,
            __uint_as_float((unsigned int)(acc[i][2] >> 32)) + bBv.y,
            __uint_as_float((unsigned int)(acc[i][3] & 0xffffffffull)) + bBv.z,
            __uint_as_float((unsigned int)(acc[i][3] >> 32)) + bBv.w);
        *(float4*)(out + (size_t)mrow * DD + cbase + tx * 4) = oA;
        *(float4*)(out + (size_t)mrow * DD + cbase + 64 + tx * 4) = oB;
    }
}

// ---------------------------------------------------------------------------
extern "C" void kernel_launch(void* const* d_in, const int* in_sizes, int n_in,
                              void* d_out, int out_size) {
    const float* frame = (const float*)d_in[0];   // [8, 8192, 512] f32
    const void*  bb    = d_in[1];                 // [8, 512, 2] int32 or int64
    const float* W     = (const float*)d_in[2];   // [544, 512] f32
    const float* bias  = (const float*)d_in[3];   // [512] f32
    float* out = (float*)d_out;                   // [8, 512, 512] f32

    k_detect<<<1, 256>>>((const unsigned int*)bb);
    k_bounds<<<16, 256>>>(bb);
    k_four<<<MM, 32>>>();
    k_sumpre<<<BB * NG, 128>>>((const float4*)frame);
    k_gscan<<<128, 256>>>();
    k_seg<<<BB * MM, 128>>>((const float4*)frame);
    dim3 g(NROWS / 128, DD / 128);
    k_gemm<<<g, 256>>>(W, bias, out);
}

// round 9
// speedup vs baseline: 2.7743x; 1.0343x over previous
#include <cuda_runtime.h>
#include <cuda_bf16.h>
#include <cstdint>

#define BB 8
#define TT 8192
#define DD 512
#define MM 512
#define KIN 544        // DD + 32 fourier dims (= 34 k-steps of 16)
#define CH 8           // rows per chunk
#define NC 1024        // TT / CH chunks per batch
#define GRP 8          // chunks per group
#define NG 128         // groups per batch (NC / GRP)
#define D4 128         // DD / 4
#define NROWS (BB*MM)  // 4096 output rows
#define NKT 34         // k-steps per product
#define NIT 102        // 3 products x 34 k-steps

// Scratch (allocation-free rule: __device__ globals)
__device__ float g_cpre[BB * NC * DD];        // 16.8 MB within-group exclusive chunk prefix
__device__ float g_gtot[BB * NG * DD];        //  2.1 MB group totals
__device__ float g_gpre[BB * (NG + 1) * DD];  //  2.1 MB exclusive group prefix
__device__ __nv_bfloat16 g_Xhi[NROWS * KIN];  //  4.5 MB X split-high [row][k]
__device__ __nv_bfloat16 g_Xlo[NROWS * KIN];  //  4.5 MB X split-low
__device__ __nv_bfloat16 g_Whi[KIN * DD];     //  0.56 MB W split-high [k][n]
__device__ __nv_bfloat16 g_Wlo[KIN * DD];     //  0.56 MB W split-low
__device__ int2  g_se  [NROWS];               // clamped (s, e) per segment
__device__ int   g_is64;

__device__ __forceinline__ uint32_t smem_u32(const void* p) {
    uint32_t a;
    asm("{ .reg .u64 t; cvta.to.shared.u64 t, %1; cvt.u32.u64 %0, t; }" : "=r"(a) : "l"(p));
    return a;
}

// ---------------------------------------------------------------------------
// K0: detect int32 vs int64 beat_bounds layout (values < 8192, so int64 has
// every odd 32-bit word zero).
// ---------------------------------------------------------------------------
__global__ void k_detect(const unsigned int* __restrict__ bb) {
    __shared__ int s_any;
    if (threadIdx.x == 0) s_any = 0;
    __syncthreads();
    int bad = 0;
    for (int i = 2 * threadIdx.x + 1; i < BB * MM * 2; i += 2 * blockDim.x)
        if (bb[i] != 0u) bad = 1;
    if (bad) atomicOr(&s_any, 1);
    __syncthreads();
    if (threadIdx.x == 0) g_is64 = (s_any == 0) ? 1 : 0;
}

// ---------------------------------------------------------------------------
// K0b: clamp bounds once into g_se.
// ---------------------------------------------------------------------------
__global__ void k_bounds(const void* __restrict__ bbv) {
    int bm = blockIdx.x * blockDim.x + threadIdx.x;
    if (bm >= NROWS) return;
    long long s_raw, e_raw;
    if (g_is64) {
        const long long* p = (const long long*)bbv;
        s_raw = p[2 * bm]; e_raw = p[2 * bm + 1];
    } else {
        const int* p = (const int*)bbv;
        s_raw = p[2 * bm]; e_raw = p[2 * bm + 1];
    }
    long long sl = s_raw; if (sl < 0) sl = 0; if (sl > TT - 1) sl = TT - 1;
    long long el = e_raw; if (el > TT) el = TT; if (el < sl + 1) el = sl + 1;
    g_se[bm] = make_int2((int)sl, (int)el);
}

// ---------------------------------------------------------------------------
// K0c: fourier features -> bf16 hi/lo cols 512..543, once per (m,i),
// broadcast to all 8 batches.
// ---------------------------------------------------------------------------
__global__ void k_four() {
    int m = blockIdx.x;       // 0..511
    int i = threadIdx.x;      // 0..31
    const float pos = (float)m * (1.0f / 511.0f);
    const float step = (float)(6.907755278982137 / 15.0);  // log(1000)/15
    int fi = (i < 16) ? i : i - 16;
    float arg = (float)fi * step;
    float freq = (float)exp((double)arg);
    float ang = pos * freq;
    double angd = (double)ang;
    float v = (i < 16) ? (float)sin(angd) : (float)cos(angd);
    __nv_bfloat16 h = __float2bfloat16(v);
    __nv_bfloat16 l = __float2bfloat16(v - __bfloat162float(h));
#pragma unroll
    for (int b = 0; b < BB; b++) {
        size_t idx = (size_t)(b * MM + m) * KIN + DD + i;
        g_Xhi[idx] = h;
        g_Xlo[idx] = l;
    }
}

// ---------------------------------------------------------------------------
// K0d: W [544][512] f32 -> bf16 hi/lo, same layout. Fully coalesced.
// ---------------------------------------------------------------------------
__global__ void k_wsplit(const float* __restrict__ W) {
    int i = blockIdx.x * blockDim.x + threadIdx.x;
    if (i >= KIN * DD) return;
    float v = W[i];
    __nv_bfloat16 h = __float2bfloat16(v);
    g_Whi[i] = h;
    g_Wlo[i] = __float2bfloat16(v - __bfloat162float(h));
}

// ---------------------------------------------------------------------------
// K1: fused chunk sums + within-group exclusive prefix + group totals.
// At its DRAM floor (71.7% per round-8 ncu).
// ---------------------------------------------------------------------------
__global__ void __launch_bounds__(128) k_sumpre(const float4* __restrict__ fr) {
    int b = blockIdx.x >> 7;
    int g = blockIdx.x & (NG - 1);
    int t = threadIdx.x;
    const float4* p = fr + (size_t)(b * TT + g * GRP * CH) * D4 + t;
    float4* cp = (float4*)g_cpre + (size_t)(b * NC + g * GRP) * D4 + t;

    float4 run = make_float4(0.f, 0.f, 0.f, 0.f);
#pragma unroll
    for (int c = 0; c < GRP; c++) {
        cp[(size_t)c * D4] = run;
        float4 s = make_float4(0.f, 0.f, 0.f, 0.f);
#pragma unroll
        for (int r = 0; r < CH; r++) {
            float4 v = p[(size_t)(c * CH + r) * D4];
            s.x += v.x; s.y += v.y; s.z += v.z; s.w += v.w;
        }
        run.x += s.x; run.y += s.y; run.z += s.z; run.w += s.w;
    }
    ((float4*)g_gtot)[(size_t)(b * NG + g) * D4 + t] = run;
}

// ---------------------------------------------------------------------------
// K2: warp-parallel exclusive prefix over 128 group totals.
// ---------------------------------------------------------------------------
__global__ void __launch_bounds__(256) k_gscan() {
    int wid = threadIdx.x >> 5, l = threadIdx.x & 31;
    int b  = blockIdx.x >> 4;
    int c4 = (blockIdx.x & 15) * 8 + wid;
    const float4* gt = (const float4*)g_gtot + (size_t)b * NG * D4 + c4;
    float4* gp = (float4*)g_gpre + (size_t)b * (NG + 1) * D4 + c4;

    float4 v[4];
    float4 s = make_float4(0.f, 0.f, 0.f, 0.f);
#pragma unroll
    for (int j = 0; j < 4; j++) {
        v[j] = gt[(size_t)(4 * l + j) * D4];
        s.x += v[j].x; s.y += v[j].y; s.z += v[j].z; s.w += v[j].w;
    }
    float4 inc = s;
#pragma unroll
    for (int off = 1; off < 32; off <<= 1) {
        float ux = __shfl_up_sync(0xffffffffu, inc.x, off);
        float uy = __shfl_up_sync(0xffffffffu, inc.y, off);
        float uz = __shfl_up_sync(0xffffffffu, inc.z, off);
        float uw = __shfl_up_sync(0xffffffffu, inc.w, off);
        if (l >= off) { inc.x += ux; inc.y += uy; inc.z += uz; inc.w += uw; }
    }
    float4 run = make_float4(inc.x - s.x, inc.y - s.y, inc.z - s.z, inc.w - s.w);
#pragma unroll
    for (int j = 0; j < 4; j++) {
        gp[(size_t)(4 * l + j) * D4] = run;
        run.x += v[j].x; run.y += v[j].y; run.z += v[j].z; run.w += v[j].w;
    }
    if (l == 31) gp[(size_t)NG * D4] = run;
}

// ---------------------------------------------------------------------------
// K3: per-segment mean -> bf16 hi/lo into g_Xhi/g_Xlo cols 0..511.
// Fixed-trip predicated tails (18 LDGs in flight).
// ---------------------------------------------------------------------------
__global__ void __launch_bounds__(128) k_seg(const float4* __restrict__ fr) {
    int bm = blockIdx.x;
    int b = bm >> 9;

    int2 se = g_se[bm];
    int s = se.x, e = se.y;
    int cs = s >> 3, ce = e >> 3;

    int t = threadIdx.x;  // float4 column
    const float4* CP = (const float4*)g_cpre + (size_t)b * NC * D4 + t;
    const float4* GP = (const float4*)g_gpre + (size_t)b * (NG + 1) * D4 + t;

    float4 a = GP[(size_t)(ce >> 3) * D4];
    float4 q = GP[(size_t)(cs >> 3) * D4];
    {
        float4 c1 = CP[(size_t)cs * D4];
        q.x += c1.x; q.y += c1.y; q.z += c1.z; q.w += c1.w;
        if (ce < NC) {
            float4 c2 = CP[(size_t)ce * D4];
            a.x += c2.x; a.y += c2.y; a.z += c2.z; a.w += c2.w;
        }
    }
    a.x -= q.x; a.y -= q.y; a.z -= q.z; a.w -= q.w;

    const float4* fb = fr + (size_t)b * TT * D4 + t;
    float4 ve[7], vs[7];
#pragma unroll
    for (int j = 0; j < 7; j++) {
        int r = ce * CH + j;
        ve[j] = make_float4(0.f, 0.f, 0.f, 0.f);
        if (r < e) ve[j] = fb[(size_t)r * D4];
    }
#pragma unroll
    for (int j = 0; j < 7; j++) {
        int r = cs * CH + j;
        vs[j] = make_float4(0.f, 0.f, 0.f, 0.f);
        if (r < s) vs[j] = fb[(size_t)r * D4];
    }
#pragma unroll
    for (int j = 0; j < 7; j++) {
        a.x += ve[j].x - vs[j].x;
        a.y += ve[j].y - vs[j].y;
        a.z += ve[j].z - vs[j].z;
        a.w += ve[j].w - vs[j].w;
    }
    float inv = 1.0f / (float)(e - s);
    a.x *= inv; a.y *= inv; a.z *= inv; a.w *= inv;

    __nv_bfloat162 h0, h1, l0, l1;
    h0.x = __float2bfloat16(a.x); h0.y = __float2bfloat16(a.y);
    h1.x = __float2bfloat16(a.z); h1.y = __float2bfloat16(a.w);
    l0.x = __float2bfloat16(a.x - __bfloat162float(h0.x));
    l0.y = __float2bfloat16(a.y - __bfloat162float(h0.y));
    l1.x = __float2bfloat16(a.z - __bfloat162float(h1.x));
    l1.y = __float2bfloat16(a.w - __bfloat162float(h1.y));
    size_t base = (size_t)bm * KIN + 4 * t;
    *(__nv_bfloat162*)(g_Xhi + base)     = h0;
    *(__nv_bfloat162*)(g_Xhi + base + 2) = h1;
    *(__nv_bfloat162*)(g_Xlo + base)     = l0;
    *(__nv_bfloat162*)(g_Xlo + base + 2) = l1;
}

// ---------------------------------------------------------------------------
// K4: split-bf16 tensor-core GEMM via mma.sync.m16n8k16 (baseline PTX, works
// on plain sm_103 target — unlike tcgen05). out = Xhi*Whi + Xhi*Wlo + Xlo*Whi
// + bias, fp32 accum. Block 128x128, 8 warps (4m x 2n, warp = 32x64),
// 102 k-steps of 16 (3 products x 34), double-buffered smem, conflict-free
// ldmatrix strides (A rows 48 B, B rows 272 B).
// ---------------------------------------------------------------------------
__global__ void __launch_bounds__(256)
k_gemm(const float* __restrict__ bias, float* __restrict__ out) {
    __shared__ __align__(16) unsigned char As[2][128 * 48];   // [m][k16] bf16, stride 48 B
    __shared__ __align__(16) unsigned char Bs[2][16 * 272];   // [k][n128] bf16, stride 272 B

    int tid = threadIdx.x, wid = tid >> 5, l = tid & 31;
    int rbase = blockIdx.x * 128, cbase = blockIdx.y * 128;
    int mw = (wid & 3) * 32;      // warp m offset in tile
    int nw = (wid >> 2) * 64;     // warp n offset in tile

    // global load lanes
    int arow = tid >> 1;                 // 0..127
    int akoff = (tid & 1) * 8;           // halves
    int brow = tid >> 4;                 // 0..15
    int bnoff = (tid & 15) * 8;          // halves

    const __nv_bfloat16* AP[3] = {
        g_Xhi + (size_t)(rbase + arow) * KIN + akoff,
        g_Xhi + (size_t)(rbase + arow) * KIN + akoff,
        g_Xlo + (size_t)(rbase + arow) * KIN + akoff};
    const __nv_bfloat16* BP[3] = {
        g_Whi + (size_t)brow * DD + cbase + bnoff,
        g_Wlo + (size_t)brow * DD + cbase + bnoff,
        g_Whi + (size_t)brow * DD + cbase + bnoff};

    uint32_t asb = smem_u32(As), bsb = smem_u32(Bs);
    uint32_t ast = asb + arow * 48 + (tid & 1) * 16;          // store addr in buf0
    uint32_t bst = bsb + brow * 272 + (tid & 15) * 16;
    // ldmatrix addresses (lane-dependent)
    uint32_t ald = asb + (mw + (l & 15)) * 48 + (l >> 4) * 16;   // + mt*16*48
    uint32_t bld = bsb + (l & 15) * 272 + nw * 2;                // + nt*16

    float acc[2][8][4];
#pragma unroll
    for (int mt = 0; mt < 2; mt++)
#pragma unroll
        for (int nt = 0; nt < 8; nt++)
#pragma unroll
            for (int j = 0; j < 4; j++) acc[mt][nt][j] = 0.f;

    // preload iteration 0 (p=0, kt=0)
    uint4 av = *(const uint4*)AP[0];
    uint4 bv = *(const uint4*)BP[0];
    *(uint4*)(As[0] + arow * 48 + (tid & 1) * 16) = av;
    *(uint4*)(Bs[0] + brow * 272 + (tid & 15) * 16) = bv;
    __syncthreads();

    for (int it = 0; it < NIT; it++) {
        int cb = it & 1;
        if (it + 1 < NIT) {
            int p2 = (it + 1) / NKT, kt2 = (it + 1) % NKT;
            av = *(const uint4*)(AP[p2] + kt2 * 16);
            bv = *(const uint4*)(BP[p2] + (size_t)kt2 * 16 * DD);
        }
        // compute on buffer cb
        uint32_t a_f[2][4], b_f[8][2];
        uint32_t ab = ald + cb * (128 * 48);
        uint32_t bb = bld + cb * (16 * 272);
#pragma unroll
        for (int mt = 0; mt < 2; mt++)
            asm volatile("ldmatrix.sync.aligned.m8n8.x4.shared.b16 {%0,%1,%2,%3}, [%4];"
                         : "=r"(a_f[mt][0]), "=r"(a_f[mt][1]), "=r"(a_f[mt][2]), "=r"(a_f[mt][3])
                         : "r"(ab + mt * 16 * 48));
#pragma unroll
        for (int nt = 0; nt < 8; nt++)
            asm volatile("ldmatrix.sync.aligned.m8n8.x2.trans.shared.b16 {%0,%1}, [%2];"
                         : "=r"(b_f[nt][0]), "=r"(b_f[nt][1])
                         : "r"(bb + nt * 16));
#pragma unroll
        for (int mt = 0; mt < 2; mt++)
#pragma unroll
            for (int nt = 0; nt < 8; nt++)
                asm volatile(
                    "mma.sync.aligned.m16n8k16.row.col.f32.bf16.bf16.f32 "
                    "{%0,%1,%2,%3}, {%4,%5,%6,%7}, {%8,%9}, {%0,%1,%2,%3};"
                    : "+f"(acc[mt][nt][0]), "+f"(acc[mt][nt][1]),
                      "+f"(acc[mt][nt][2]), "+f"(acc[mt][nt][3])
                    : "r"(a_f[mt][0]), "r"(a_f[mt][1]), "r"(a_f[mt][2]), "r"(a_f[mt][3]),
                      "r"(b_f[nt][0]), "r"(b_f[nt][1]));
        if (it + 1 < NIT) {
            int nb = cb ^ 1;
            *(uint4*)((unsigned char*)As[nb] + arow * 48 + (tid & 1) * 16) = av;
            *(uint4*)((unsigned char*)Bs[nb] + brow * 272 + (tid & 15) * 16) = bv;
        }
        __syncthreads();
    }

    // epilogue: D[g][2tg] pairs per mma tile
    int g = l >> 2, tg = l & 3;
#pragma unroll
    for (int mt = 0; mt < 2; mt++) {
#pragma unroll
        for (int nt = 0; nt < 8; nt++) {
            int col = cbase + nw + nt * 8 + 2 * tg;
            float2 bv2 = *(const float2*)(bias + col);
            int r0 = rbase + mw + mt * 16 + g;
            float2 o0 = make_float2(acc[mt][nt][0] + bv2.x, acc[mt][nt][1] + bv2.y);
            float2 o1 = make_float2(acc[mt][nt][2] + bv2.x, acc[mt][nt][3] + bv2.y);
            *(float2*)(out + (size_t)r0 * DD + col) = o0;
            *(float2*)(out + (size_t)(r0 + 8) * DD + col) = o1;
        }
    }
}

// ---------------------------------------------------------------------------
extern "C" void kernel_launch(void* const* d_in, const int* in_sizes, int n_in,
                              void* d_out, int out_size) {
    const float* frame = (const float*)d_in[0];   // [8, 8192, 512] f32
    const void*  bb    = d_in[1];                 // [8, 512, 2] int32 or int64
    const float* W     = (const float*)d_in[2];   // [544, 512] f32
    const float* bias  = (const float*)d_in[3];   // [512] f32
    float* out = (float*)d_out;                   // [8, 512, 512] f32

    k_detect<<<1, 256>>>((const unsigned int*)bb);
    k_bounds<<<16, 256>>>(bb);
    k_four<<<MM, 32>>>();
    k_wsplit<<<(KIN * DD + 255) / 256, 256>>>(W);
    k_sumpre<<<BB * NG, 128>>>((const float4*)frame);
    k_gscan<<<128, 256>>>();
    k_seg<<<BB * MM, 128>>>((const float4*)frame);
    dim3 g(NROWS / 128, DD / 128);
    k_gemm<<<g, 256>>>(bias, out);
}

// round 11
// speedup vs baseline: 3.1524x; 1.1363x over previous
#include <cuda_runtime.h>
#include <cuda_bf16.h>
#include <cstdint>

#define BB 8
#define TT 8192
#define DD 512
#define MM 512
#define KIN 544        // DD + 32 fourier dims
#define CH 8           // rows per chunk
#define NC 1024        // TT / CH chunks per batch
#define GRP 8          // chunks per group
#define NG 128         // groups per batch (NC / GRP)
#define D4 128         // DD / 4
#define NROWS (BB*MM)  // 4096 output rows
#define NKS 17         // k32-steps per product (544/32)
#define NIT 51         // 3 products x 17
#define NB_WS 1088     // wsplit blocks (KIN*DD/256)
#define NB_F  64       // fourier blocks

// Scratch (allocation-free rule: __device__ globals)
__device__ float g_cpre[BB * NC * DD];        // 16.8 MB within-group exclusive chunk prefix
__device__ float g_gtot[BB * NG * DD];        //  2.1 MB group totals
__device__ float g_gpre[BB * (NG + 1) * DD];  //  2.1 MB exclusive group prefix
__device__ __nv_bfloat16 g_Xhi[NROWS * KIN];  //  4.5 MB X split-high [row][k]
__device__ __nv_bfloat16 g_Xlo[NROWS * KIN];  //  4.5 MB X split-low
__device__ __nv_bfloat16 g_Whi[KIN * DD];     //  0.56 MB W split-high [k][n]
__device__ __nv_bfloat16 g_Wlo[KIN * DD];     //  0.56 MB W split-low
__device__ int2  g_se  [NROWS];               // clamped (s, e) per segment
__device__ int   g_is64;

__device__ __forceinline__ uint32_t smem_u32(const void* p) {
    uint32_t a;
    asm("{ .reg .u64 t; cvta.to.shared.u64 t, %1; cvt.u32.u64 %0, t; }" : "=r"(a) : "l"(p));
    return a;
}

// ---------------------------------------------------------------------------
// K_prep: fused prep. blocks [0,1088): W split; [1088,1152): fourier;
// block 1152: int32/int64 detection. One launch instead of three.
// ---------------------------------------------------------------------------
__global__ void __launch_bounds__(256) k_prep(const float* __restrict__ W,
                                              const unsigned int* __restrict__ bb) {
    int bid = blockIdx.x, tid = threadIdx.x;
    if (bid < NB_WS) {
        int i = bid * 256 + tid;
        float v = W[i];
        __nv_bfloat16 h = __float2bfloat16(v);
        g_Whi[i] = h;
        g_Wlo[i] = __float2bfloat16(v - __bfloat162float(h));
    } else if (bid < NB_WS + NB_F) {
        int m = (bid - NB_WS) * 8 + (tid >> 5);
        int i = tid & 31;
        const float pos = (float)m * (1.0f / 511.0f);
        const float step = (float)(6.907755278982137 / 15.0);  // log(1000)/15
        int fi = (i < 16) ? i : i - 16;
        float arg = (float)fi * step;
        float freq = (float)exp((double)arg);
        float ang = pos * freq;
        double angd = (double)ang;
        float v = (i < 16) ? (float)sin(angd) : (float)cos(angd);
        __nv_bfloat16 h = __float2bfloat16(v);
        __nv_bfloat16 l = __float2bfloat16(v - __bfloat162float(h));
#pragma unroll
        for (int b = 0; b < BB; b++) {
            size_t idx = (size_t)(b * MM + m) * KIN + DD + i;
            g_Xhi[idx] = h;
            g_Xlo[idx] = l;
        }
    } else {
        __shared__ int s_any;
        if (tid == 0) s_any = 0;
        __syncthreads();
        int bad = 0;
        for (int i = 2 * tid + 1; i < BB * MM * 2; i += 2 * 256)
            if (bb[i] != 0u) bad = 1;
        if (bad) atomicOr(&s_any, 1);
        __syncthreads();
        if (tid == 0) g_is64 = (s_any == 0) ? 1 : 0;
    }
}

// ---------------------------------------------------------------------------
// K0b: clamp bounds once into g_se.
// ---------------------------------------------------------------------------
__global__ void k_bounds(const void* __restrict__ bbv) {
    int bm = blockIdx.x * blockDim.x + threadIdx.x;
    if (bm >= NROWS) return;
    long long s_raw, e_raw;
    if (g_is64) {
        const long long* p = (const long long*)bbv;
        s_raw = p[2 * bm]; e_raw = p[2 * bm + 1];
    } else {
        const int* p = (const int*)bbv;
        s_raw = p[2 * bm]; e_raw = p[2 * bm + 1];
    }
    long long sl = s_raw; if (sl < 0) sl = 0; if (sl > TT - 1) sl = TT - 1;
    long long el = e_raw; if (el > TT) el = TT; if (el < sl + 1) el = sl + 1;
    g_se[bm] = make_int2((int)sl, (int)el);
}

// ---------------------------------------------------------------------------
// K1: fused chunk sums + within-group exclusive prefix + group totals.
// At its DRAM floor (71.7% per round-8 ncu).
// ---------------------------------------------------------------------------
__global__ void __launch_bounds__(128) k_sumpre(const float4* __restrict__ fr) {
    int b = blockIdx.x >> 7;
    int g = blockIdx.x & (NG - 1);
    int t = threadIdx.x;
    const float4* p = fr + (size_t)(b * TT + g * GRP * CH) * D4 + t;
    float4* cp = (float4*)g_cpre + (size_t)(b * NC + g * GRP) * D4 + t;

    float4 run = make_float4(0.f, 0.f, 0.f, 0.f);
#pragma unroll
    for (int c = 0; c < GRP; c++) {
        cp[(size_t)c * D4] = run;
        float4 s = make_float4(0.f, 0.f, 0.f, 0.f);
#pragma unroll
        for (int r = 0; r < CH; r++) {
            float4 v = p[(size_t)(c * CH + r) * D4];
            s.x += v.x; s.y += v.y; s.z += v.z; s.w += v.w;
        }
        run.x += s.x; run.y += s.y; run.z += s.z; run.w += s.w;
    }
    ((float4*)g_gtot)[(size_t)(b * NG + g) * D4 + t] = run;
}

// ---------------------------------------------------------------------------
// K2: warp-parallel exclusive prefix over 128 group totals.
// ---------------------------------------------------------------------------
__global__ void __launch_bounds__(256) k_gscan() {
    int wid = threadIdx.x >> 5, l = threadIdx.x & 31;
    int b  = blockIdx.x >> 4;
    int c4 = (blockIdx.x & 15) * 8 + wid;
    const float4* gt = (const float4*)g_gtot + (size_t)b * NG * D4 + c4;
    float4* gp = (float4*)g_gpre + (size_t)b * (NG + 1) * D4 + c4;

    float4 v[4];
    float4 s = make_float4(0.f, 0.f, 0.f, 0.f);
#pragma unroll
    for (int j = 0; j < 4; j++) {
        v[j] = gt[(size_t)(4 * l + j) * D4];
        s.x += v[j].x; s.y += v[j].y; s.z += v[j].z; s.w += v[j].w;
    }
    float4 inc = s;
#pragma unroll
    for (int off = 1; off < 32; off <<= 1) {
        float ux = __shfl_up_sync(0xffffffffu, inc.x, off);
        float uy = __shfl_up_sync(0xffffffffu, inc.y, off);
        float uz = __shfl_up_sync(0xffffffffu, inc.z, off);
        float uw = __shfl_up_sync(0xffffffffu, inc.w, off);
        if (l >= off) { inc.x += ux; inc.y += uy; inc.z += uz; inc.w += uw; }
    }
    float4 run = make_float4(inc.x - s.x, inc.y - s.y, inc.z - s.z, inc.w - s.w);
#pragma unroll
    for (int j = 0; j < 4; j++) {
        gp[(size_t)(4 * l + j) * D4] = run;
        run.x += v[j].x; run.y += v[j].y; run.z += v[j].z; run.w += v[j].w;
    }
    if (l == 31) gp[(size_t)NG * D4] = run;
}

// ---------------------------------------------------------------------------
// K3: per-segment mean -> bf16 hi/lo into g_Xhi/g_Xlo cols 0..511.
// ---------------------------------------------------------------------------
__global__ void __launch_bounds__(128) k_seg(const float4* __restrict__ fr) {
    int bm = blockIdx.x;
    int b = bm >> 9;

    int2 se = g_se[bm];
    int s = se.x, e = se.y;
    int cs = s >> 3, ce = e >> 3;

    int t = threadIdx.x;
    const float4* CP = (const float4*)g_cpre + (size_t)b * NC * D4 + t;
    const float4* GP = (const float4*)g_gpre + (size_t)b * (NG + 1) * D4 + t;

    float4 a = GP[(size_t)(ce >> 3) * D4];
    float4 q = GP[(size_t)(cs >> 3) * D4];
    {
        float4 c1 = CP[(size_t)cs * D4];
        q.x += c1.x; q.y += c1.y; q.z += c1.z; q.w += c1.w;
        if (ce < NC) {
            float4 c2 = CP[(size_t)ce * D4];
            a.x += c2.x; a.y += c2.y; a.z += c2.z; a.w += c2.w;
        }
    }
    a.x -= q.x; a.y -= q.y; a.z -= q.z; a.w -= q.w;

    const float4* fb = fr + (size_t)b * TT * D4 + t;
    float4 ve[7], vs[7];
#pragma unroll
    for (int j = 0; j < 7; j++) {
        int r = ce * CH + j;
        ve[j] = make_float4(0.f, 0.f, 0.f, 0.f);
        if (r < e) ve[j] = fb[(size_t)r * D4];
    }
#pragma unroll
    for (int j = 0; j < 7; j++) {
        int r = cs * CH + j;
        vs[j] = make_float4(0.f, 0.f, 0.f, 0.f);
        if (r < s) vs[j] = fb[(size_t)r * D4];
    }
#pragma unroll
    for (int j = 0; j < 7; j++) {
        a.x += ve[j].x - vs[j].x;
        a.y += ve[j].y - vs[j].y;
        a.z += ve[j].z - vs[j].z;
        a.w += ve[j].w - vs[j].w;
    }
    float inv = 1.0f / (float)(e - s);
    a.x *= inv; a.y *= inv; a.z *= inv; a.w *= inv;

    __nv_bfloat162 h0, h1, l0, l1;
    h0.x = __float2bfloat16(a.x); h0.y = __float2bfloat16(a.y);
    h1.x = __float2bfloat16(a.z); h1.y = __float2bfloat16(a.w);
    l0.x = __float2bfloat16(a.x - __bfloat162float(h0.x));
    l0.y = __float2bfloat16(a.y - __bfloat162float(h0.y));
    l1.x = __float2bfloat16(a.z - __bfloat162float(h1.x));
    l1.y = __float2bfloat16(a.w - __bfloat162float(h1.y));
    size_t base = (size_t)bm * KIN + 4 * t;
    *(__nv_bfloat162*)(g_Xhi + base)     = h0;
    *(__nv_bfloat162*)(g_Xhi + base + 2) = h1;
    *(__nv_bfloat162*)(g_Xlo + base)     = l0;
    *(__nv_bfloat162*)(g_Xlo + base + 2) = l1;
}

// ---------------------------------------------------------------------------
// K4: split-bf16 mma.sync GEMM, 64x128 tile, 256 blocks (all SMs busy),
// K-step 32 per buffer (51 syncs vs 102), B via x4.trans ldmatrix.
// 8 warps: (wid&3)->m 16-row slice, (wid>>2)->n 64-col slice.
// ---------------------------------------------------------------------------
__global__ void __launch_bounds__(256)
k_gemm(const float* __restrict__ bias, float* __restrict__ out) {
    __shared__ __align__(16) unsigned char As[2][64 * 80];    // [m][k32] bf16, pitch 80 B
    __shared__ __align__(16) unsigned char Bs[2][32 * 272];   // [k32][n128] bf16, pitch 272 B

    int tid = threadIdx.x, wid = tid >> 5, l = tid & 31;
    int rbase = blockIdx.x * 64, cbase = blockIdx.y * 128;
    int mw = (wid & 3) * 16;
    int nw = (wid >> 2) * 64;

    int arow = tid >> 2;                 // 0..63
    int ak = (tid & 3) * 8;              // k element offset
    int brow = tid >> 3;                 // 0..31
    int bn = (tid & 7) * 16;             // n element offset

    const __nv_bfloat16* AP[3] = {
        g_Xhi + (size_t)(rbase + arow) * KIN + ak,
        g_Xhi + (size_t)(rbase + arow) * KIN + ak,
        g_Xlo + (size_t)(rbase + arow) * KIN + ak};
    const __nv_bfloat16* BP[3] = {
        g_Whi + (size_t)brow * DD + cbase + bn,
        g_Wlo + (size_t)brow * DD + cbase + bn,
        g_Whi + (size_t)brow * DD + cbase + bn};

    uint32_t asb = smem_u32(As), bsb = smem_u32(Bs);
    uint32_t ald = asb + (mw + (l & 15)) * 80 + (l >> 4) * 16;
    uint32_t bg = l >> 3;
    uint32_t bld = bsb + (((bg & 1) * 8) + (l & 7)) * 272 + (nw + (bg >> 1) * 8) * 2;

    float acc[8][4];
#pragma unroll
    for (int nt = 0; nt < 8; nt++)
#pragma unroll
        for (int j = 0; j < 4; j++) acc[nt][j] = 0.f;

    uint4 av = *(const uint4*)AP[0];
    uint4 bv0 = *(const uint4*)BP[0];
    uint4 bv1 = *(const uint4*)(BP[0] + 8);
    *(uint4*)(As[0] + arow * 80 + (tid & 3) * 16) = av;
    *(uint4*)(Bs[0] + brow * 272 + (tid & 7) * 32) = bv0;
    *(uint4*)(Bs[0] + brow * 272 + (tid & 7) * 32 + 16) = bv1;
    __syncthreads();

    int p2 = 0, kt2 = 0;
    for (int it = 0; it < NIT; it++) {
        int cb = it & 1;
        if (it + 1 < NIT) {
            if (++kt2 == NKS) { kt2 = 0; p2++; }
            av  = *(const uint4*)(AP[p2] + kt2 * 32);
            bv0 = *(const uint4*)(BP[p2] + (size_t)kt2 * 32 * DD);
            bv1 = *(const uint4*)(BP[p2] + (size_t)kt2 * 32 * DD + 8);
        }
        uint32_t ab = ald + cb * (64 * 80);
        uint32_t bb = bld + cb * (32 * 272);
#pragma unroll
        for (int kk = 0; kk < 2; kk++) {
            uint32_t a_f[4];
            asm volatile("ldmatrix.sync.aligned.m8n8.x4.shared.b16 {%0,%1,%2,%3}, [%4];"
                         : "=r"(a_f[0]), "=r"(a_f[1]), "=r"(a_f[2]), "=r"(a_f[3])
                         : "r"(ab + kk * 32));
            uint32_t b_f[8][2];
#pragma unroll
            for (int pr = 0; pr < 4; pr++)
                asm volatile("ldmatrix.sync.aligned.m8n8.x4.trans.shared.b16 {%0,%1,%2,%3}, [%4];"
                             : "=r"(b_f[2 * pr][0]), "=r"(b_f[2 * pr][1]),
                               "=r"(b_f[2 * pr + 1][0]), "=r"(b_f[2 * pr + 1][1])
                             : "r"(bb + kk * (16 * 272) + pr * 32));
#pragma unroll
            for (int nt = 0; nt < 8; nt++)
                asm volatile(
                    "mma.sync.aligned.m16n8k16.row.col.f32.bf16.bf16.f32 "
                    "{%0,%1,%2,%3}, {%4,%5,%6,%7}, {%8,%9}, {%0,%1,%2,%3};"
                    : "+f"(acc[nt][0]), "+f"(acc[nt][1]), "+f"(acc[nt][2]), "+f"(acc[nt][3])
                    : "r"(a_f[0]), "r"(a_f[1]), "r"(a_f[2]), "r"(a_f[3]),
                      "r"(b_f[nt][0]), "r"(b_f[nt][1]));
        }
        if (it + 1 < NIT) {
            int nb = cb ^ 1;
            *(uint4*)(As[nb] + arow * 80 + (tid & 3) * 16) = av;
            *(uint4*)(Bs[nb] + brow * 272 + (tid & 7) * 32) = bv0;
            *(uint4*)(Bs[nb] + brow * 272 + (tid & 7) * 32 + 16) = bv1;
        }
        __syncthreads();
    }

    int g = l >> 2, tg = l & 3;
#pragma unroll
    for (int nt = 0; nt < 8; nt++) {
        int col = cbase + nw + nt * 8 + 2 * tg;
        float2 bv2 = *(const float2*)(bias + col);
        int r0 = rbase + mw + g;
        float2 o0 = make_float2(acc[nt][0] + bv2.x, acc[nt][1] + bv2.y);
        float2 o1 = make_float2(acc[nt][2] + bv2.x, acc[nt][3] + bv2.y);
        *(float2*)(out + (size_t)r0 * DD + col) = o0;
        *(float2*)(out + (size_t)(r0 + 8) * DD + col) = o1;
    }
}

// ---------------------------------------------------------------------------
extern "C" void kernel_launch(void* const* d_in, const int* in_sizes, int n_in,
                              void* d_out, int out_size) {
    const float* frame = (const float*)d_in[0];   // [8, 8192, 512] f32
    const void*  bb    = d_in[1];                 // [8, 512, 2] int32 or int64
    const float* W     = (const float*)d_in[2];   // [544, 512] f32
    const float* bias  = (const float*)d_in[3];   // [512] f32
    float* out = (float*)d_out;                   // [8, 512, 512] f32

    k_prep<<<NB_WS + NB_F + 1, 256>>>(W, (const unsigned int*)bb);
    k_bounds<<<16, 256>>>(bb);
    k_sumpre<<<BB * NG, 128>>>((const float4*)frame);
    k_gscan<<<128, 256>>>();
    k_seg<<<BB * MM, 128>>>((const float4*)frame);
    dim3 g(NROWS / 64, DD / 128);
    k_gemm<<<g, 256>>>(bias, out);
}

// round 12
// speedup vs baseline: 3.5717x; 1.1330x over previous
#include <cuda_runtime.h>
#include <cuda_bf16.h>
#include <cstdint>

#define BB 8
#define TT 8192
#define DD 512
#define MM 512
#define KIN 544        // DD + 32 fourier dims
#define CH 8           // rows per chunk
#define NC 1024        // TT / CH chunks per batch
#define GRP 8          // chunks per group
#define NG 128         // groups per batch (NC / GRP)
#define D4 128         // DD / 4
#define NROWS (BB*MM)  // 4096 output rows
#define NKS 17         // k32-steps per product (544/32)
#define NIT 51         // 3 products x 17

// combo1 block ranges
#define NB_SUM 512     // sumpre: 2 groups per block
#define NB_WS  1088    // wsplit (KIN*DD/256)
#define NB_F   64      // fourier
#define NB_BND 16      // bounds (4096/256)

// Scratch (allocation-free rule: __device__ globals)
__device__ float g_cpre[BB * NC * DD];        // 16.8 MB within-group exclusive chunk prefix
__device__ float g_gtot[BB * NG * DD];        //  2.1 MB group totals
__device__ float g_gpre[BB * (NG + 1) * DD];  //  2.1 MB exclusive group prefix
__device__ __nv_bfloat16 g_Xhi[NROWS * KIN];  //  4.5 MB X split-high [row][k]
__device__ __nv_bfloat16 g_Xlo[NROWS * KIN];  //  4.5 MB X split-low
__device__ __nv_bfloat16 g_Whi[KIN * DD];     //  0.56 MB W split-high [k][n]
__device__ __nv_bfloat16 g_Wlo[KIN * DD];     //  0.56 MB W split-low
__device__ int2  g_se  [NROWS];               // clamped (s, e) per segment

__device__ __forceinline__ uint32_t smem_u32(const void* p) {
    uint32_t a;
    asm("{ .reg .u64 t; cvta.to.shared.u64 t, %1; cvt.u32.u64 %0, t; }" : "=r"(a) : "l"(p));
    return a;
}

// ---------------------------------------------------------------------------
// K_combo1: ONE launch for all independent front work (block-range dispatch):
//   [0, 512)        chunk sums + within-group prefix + group totals (2 grp/blk)
//   [512, 1600)     W f32 -> bf16 hi/lo split
//   [1600, 1664)    fourier features -> g_Xhi/g_Xlo cols 512..543
//   [1664, 1680)    bounds clamp, with per-block int64 self-detection
// Prep/bounds hide under the DRAM-bound sumpre wave; removes 2 launches + the
// serialized detect->bounds dependency.
// ---------------------------------------------------------------------------
__global__ void __launch_bounds__(256) k_combo1(const float4* __restrict__ fr,
                                                const float* __restrict__ W,
                                                const void* __restrict__ bbv) {
    int bid = blockIdx.x, tid = threadIdx.x;

    if (bid < NB_SUM) {
        // ---- sumpre: block handles (b, 2 groups); threads split 128/128 ----
        int b = bid >> 6;
        int g = (bid & 63) * 2 + (tid >> 7);
        int t = tid & 127;
        const float4* p = fr + (size_t)(b * TT + g * GRP * CH) * D4 + t;
        float4* cp = (float4*)g_cpre + (size_t)(b * NC + g * GRP) * D4 + t;

        float4 run = make_float4(0.f, 0.f, 0.f, 0.f);
#pragma unroll
        for (int c = 0; c < GRP; c++) {
            cp[(size_t)c * D4] = run;
            float4 s = make_float4(0.f, 0.f, 0.f, 0.f);
#pragma unroll
            for (int r = 0; r < CH; r++) {
                float4 v = p[(size_t)(c * CH + r) * D4];
                s.x += v.x; s.y += v.y; s.z += v.z; s.w += v.w;
            }
            run.x += s.x; run.y += s.y; run.z += s.z; run.w += s.w;
        }
        ((float4*)g_gtot)[(size_t)(b * NG + g) * D4 + t] = run;

    } else if (bid < NB_SUM + NB_WS) {
        // ---- W split ----
        int i = (bid - NB_SUM) * 256 + tid;
        float v = W[i];
        __nv_bfloat16 h = __float2bfloat16(v);
        g_Whi[i] = h;
        g_Wlo[i] = __float2bfloat16(v - __bfloat162float(h));

    } else if (bid < NB_SUM + NB_WS + NB_F) {
        // ---- fourier ----
        int m = (bid - NB_SUM - NB_WS) * 8 + (tid >> 5);
        int i = tid & 31;
        const float pos = (float)m * (1.0f / 511.0f);
        const float step = (float)(6.907755278982137 / 15.0);  // log(1000)/15
        int fi = (i < 16) ? i : i - 16;
        float arg = (float)fi * step;
        float freq = (float)exp((double)arg);
        float ang = pos * freq;
        double angd = (double)ang;
        float v = (i < 16) ? (float)sin(angd) : (float)cos(angd);
        __nv_bfloat16 h = __float2bfloat16(v);
        __nv_bfloat16 l = __float2bfloat16(v - __bfloat162float(h));
#pragma unroll
        for (int b = 0; b < BB; b++) {
            size_t idx = (size_t)(b * MM + m) * KIN + DD + i;
            g_Xhi[idx] = h;
            g_Xlo[idx] = l;
        }

    } else {
        // ---- bounds with self-detection (values < 8192 => int64 has all odd
        // 32-bit words zero; the 32 KB scan is L2-hot and per-block) ----
        __shared__ int s_any;
        if (tid == 0) s_any = 0;
        __syncthreads();
        const unsigned int* bbw = (const unsigned int*)bbv;
        int bad = 0;
        for (int i = 2 * tid + 1; i < BB * MM * 2; i += 2 * 256)
            if (bbw[i] != 0u) bad = 1;
        if (bad) atomicOr(&s_any, 1);
        __syncthreads();
        int is64 = (s_any == 0);

        int bm = (bid - NB_SUM - NB_WS - NB_F) * 256 + tid;
        long long s_raw, e_raw;
        if (is64) {
            const long long* p = (const long long*)bbv;
            s_raw = p[2 * bm]; e_raw = p[2 * bm + 1];
        } else {
            const int* p = (const int*)bbv;
            s_raw = p[2 * bm]; e_raw = p[2 * bm + 1];
        }
        long long sl = s_raw; if (sl < 0) sl = 0; if (sl > TT - 1) sl = TT - 1;
        long long el = e_raw; if (el > TT) el = TT; if (el < sl + 1) el = sl + 1;
        g_se[bm] = make_int2((int)sl, (int)el);
    }
}

// ---------------------------------------------------------------------------
// K2: warp-parallel exclusive prefix over 128 group totals.
// ---------------------------------------------------------------------------
__global__ void __launch_bounds__(256) k_gscan() {
    int wid = threadIdx.x >> 5, l = threadIdx.x & 31;
    int b  = blockIdx.x >> 4;
    int c4 = (blockIdx.x & 15) * 8 + wid;
    const float4* gt = (const float4*)g_gtot + (size_t)b * NG * D4 + c4;
    float4* gp = (float4*)g_gpre + (size_t)b * (NG + 1) * D4 + c4;

    float4 v[4];
    float4 s = make_float4(0.f, 0.f, 0.f, 0.f);
#pragma unroll
    for (int j = 0; j < 4; j++) {
        v[j] = gt[(size_t)(4 * l + j) * D4];
        s.x += v[j].x; s.y += v[j].y; s.z += v[j].z; s.w += v[j].w;
    }
    float4 inc = s;
#pragma unroll
    for (int off = 1; off < 32; off <<= 1) {
        float ux = __shfl_up_sync(0xffffffffu, inc.x, off);
        float uy = __shfl_up_sync(0xffffffffu, inc.y, off);
        float uz = __shfl_up_sync(0xffffffffu, inc.z, off);
        float uw = __shfl_up_sync(0xffffffffu, inc.w, off);
        if (l >= off) { inc.x += ux; inc.y += uy; inc.z += uz; inc.w += uw; }
    }
    float4 run = make_float4(inc.x - s.x, inc.y - s.y, inc.z - s.z, inc.w - s.w);
#pragma unroll
    for (int j = 0; j < 4; j++) {
        gp[(size_t)(4 * l + j) * D4] = run;
        run.x += v[j].x; run.y += v[j].y; run.z += v[j].z; run.w += v[j].w;
    }
    if (l == 31) gp[(size_t)NG * D4] = run;
}

// ---------------------------------------------------------------------------
// K3: per-segment mean -> bf16 hi/lo into g_Xhi/g_Xlo cols 0..511.
// ---------------------------------------------------------------------------
__global__ void __launch_bounds__(128) k_seg(const float4* __restrict__ fr) {
    int bm = blockIdx.x;
    int b = bm >> 9;

    int2 se = g_se[bm];
    int s = se.x, e = se.y;
    int cs = s >> 3, ce = e >> 3;

    int t = threadIdx.x;
    const float4* CP = (const float4*)g_cpre + (size_t)b * NC * D4 + t;
    const float4* GP = (const float4*)g_gpre + (size_t)b * (NG + 1) * D4 + t;

    float4 a = GP[(size_t)(ce >> 3) * D4];
    float4 q = GP[(size_t)(cs >> 3) * D4];
    {
        float4 c1 = CP[(size_t)cs * D4];
        q.x += c1.x; q.y += c1.y; q.z += c1.z; q.w += c1.w;
        if (ce < NC) {
            float4 c2 = CP[(size_t)ce * D4];
            a.x += c2.x; a.y += c2.y; a.z += c2.z; a.w += c2.w;
        }
    }
    a.x -= q.x; a.y -= q.y; a.z -= q.z; a.w -= q.w;

    const float4* fb = fr + (size_t)b * TT * D4 + t;
    float4 ve[7], vs[7];
#pragma unroll
    for (int j = 0; j < 7; j++) {
        int r = ce * CH + j;
        ve[j] = make_float4(0.f, 0.f, 0.f, 0.f);
        if (r < e) ve[j] = fb[(size_t)r * D4];
    }
#pragma unroll
    for (int j = 0; j < 7; j++) {
        int r = cs * CH + j;
        vs[j] = make_float4(0.f, 0.f, 0.f, 0.f);
        if (r < s) vs[j] = fb[(size_t)r * D4];
    }
#pragma unroll
    for (int j = 0; j < 7; j++) {
        a.x += ve[j].x - vs[j].x;
        a.y += ve[j].y - vs[j].y;
        a.z += ve[j].z - vs[j].z;
        a.w += ve[j].w - vs[j].w;
    }
    float inv = 1.0f / (float)(e - s);
    a.x *= inv; a.y *= inv; a.z *= inv; a.w *= inv;

    __nv_bfloat162 h0, h1, l0, l1;
    h0.x = __float2bfloat16(a.x); h0.y = __float2bfloat16(a.y);
    h1.x = __float2bfloat16(a.z); h1.y = __float2bfloat16(a.w);
    l0.x = __float2bfloat16(a.x - __bfloat162float(h0.x));
    l0.y = __float2bfloat16(a.y - __bfloat162float(h0.y));
    l1.x = __float2bfloat16(a.z - __bfloat162float(h1.x));
    l1.y = __float2bfloat16(a.w - __bfloat162float(h1.y));
    size_t base = (size_t)bm * KIN + 4 * t;
    *(__nv_bfloat162*)(g_Xhi + base)     = h0;
    *(__nv_bfloat162*)(g_Xhi + base + 2) = h1;
    *(__nv_bfloat162*)(g_Xlo + base)     = l0;
    *(__nv_bfloat162*)(g_Xlo + base + 2) = l1;
}

// ---------------------------------------------------------------------------
// K4: split-bf16 mma.sync GEMM, 64x128 tile, 256 blocks, K-step 32/buffer,
// B via x4.trans ldmatrix. (Validated round 11.)
// ---------------------------------------------------------------------------
__global__ void __launch_bounds__(256)
k_gemm(const float* __restrict__ bias, float* __restrict__ out) {
    __shared__ __align__(16) unsigned char As[2][64 * 80];    // [m][k32] bf16, pitch 80 B
    __shared__ __align__(16) unsigned char Bs[2][32 * 272];   // [k32][n128] bf16, pitch 272 B

    int tid = threadIdx.x, wid = tid >> 5, l = tid & 31;
    int rbase = blockIdx.x * 64, cbase = blockIdx.y * 128;
    int mw = (wid & 3) * 16;
    int nw = (wid >> 2) * 64;

    int arow = tid >> 2;
    int ak = (tid & 3) * 8;
    int brow = tid >> 3;
    int bn = (tid & 7) * 16;

    const __nv_bfloat16* AP[3] = {
        g_Xhi + (size_t)(rbase + arow) * KIN + ak,
        g_Xhi + (size_t)(rbase + arow) * KIN + ak,
        g_Xlo + (size_t)(rbase + arow) * KIN + ak};
    const __nv_bfloat16* BP[3] = {
        g_Whi + (size_t)brow * DD + cbase + bn,
        g_Wlo + (size_t)brow * DD + cbase + bn,
        g_Whi + (size_t)brow * DD + cbase + bn};

    uint32_t asb = smem_u32(As), bsb = smem_u32(Bs);
    uint32_t ald = asb + (mw + (l & 15)) * 80 + (l >> 4) * 16;
    uint32_t bg = l >> 3;
    uint32_t bld = bsb + (((bg & 1) * 8) + (l & 7)) * 272 + (nw + (bg >> 1) * 8) * 2;

    float acc[8][4];
#pragma unroll
    for (int nt = 0; nt < 8; nt++)
#pragma unroll
        for (int j = 0; j < 4; j++) acc[nt][j] = 0.f;

    uint4 av = *(const uint4*)AP[0];
    uint4 bv0 = *(const uint4*)BP[0];
    uint4 bv1 = *(const uint4*)(BP[0] + 8);
    *(uint4*)(As[0] + arow * 80 + (tid & 3) * 16) = av;
    *(uint4*)(Bs[0] + brow * 272 + (tid & 7) * 32) = bv0;
    *(uint4*)(Bs[0] + brow * 272 + (tid & 7) * 32 + 16) = bv1;
    __syncthreads();

    int p2 = 0, kt2 = 0;
    for (int it = 0; it < NIT; it++) {
        int cb = it & 1;
        if (it + 1 < NIT) {
            if (++kt2 == NKS) { kt2 = 0; p2++; }
            av  = *(const uint4*)(AP[p2] + kt2 * 32);
            bv0 = *(const uint4*)(BP[p2] + (size_t)kt2 * 32 * DD);
            bv1 = *(const uint4*)(BP[p2] + (size_t)kt2 * 32 * DD + 8);
        }
        uint32_t ab = ald + cb * (64 * 80);
        uint32_t bb = bld + cb * (32 * 272);
#pragma unroll
        for (int kk = 0; kk < 2; kk++) {
            uint32_t a_f[4];
            asm volatile("ldmatrix.sync.aligned.m8n8.x4.shared.b16 {%0,%1,%2,%3}, [%4];"
                         : "=r"(a_f[0]), "=r"(a_f[1]), "=r"(a_f[2]), "=r"(a_f[3])
                         : "r"(ab + kk * 32));
            uint32_t b_f[8][2];
#pragma unroll
            for (int pr = 0; pr < 4; pr++)
                asm volatile("ldmatrix.sync.aligned.m8n8.x4.trans.shared.b16 {%0,%1,%2,%3}, [%4];"
                             : "=r"(b_f[2 * pr][0]), "=r"(b_f[2 * pr][1]),
                               "=r"(b_f[2 * pr + 1][0]), "=r"(b_f[2 * pr + 1][1])
                             : "r"(bb + kk * (16 * 272) + pr * 32));
#pragma unroll
            for (int nt = 0; nt < 8; nt++)
                asm volatile(
                    "mma.sync.aligned.m16n8k16.row.col.f32.bf16.bf16.f32 "
                    "{%0,%1,%2,%3}, {%4,%5,%6,%7}, {%8,%9}, {%0,%1,%2,%3};"
                    : "+f"(acc[nt][0]), "+f"(acc[nt][1]), "+f"(acc[nt][2]), "+f"(acc[nt][3])
                    : "r"(a_f[0]), "r"(a_f[1]), "r"(a_f[2]), "r"(a_f[3]),
                      "r"(b_f[nt][0]), "r"(b_f[nt][1]));
        }
        if (it + 1 < NIT) {
            int nb = cb ^ 1;
            *(uint4*)(As[nb] + arow * 80 + (tid & 3) * 16) = av;
            *(uint4*)(Bs[nb] + brow * 272 + (tid & 7) * 32) = bv0;
            *(uint4*)(Bs[nb] + brow * 272 + (tid & 7) * 32 + 16) = bv1;
        }
        __syncthreads();
    }

    int g = l >> 2, tg = l & 3;
#pragma unroll
    for (int nt = 0; nt < 8; nt++) {
        int col = cbase + nw + nt * 8 + 2 * tg;
        float2 bv2 = *(const float2*)(bias + col);
        int r0 = rbase + mw + g;
        float2 o0 = make_float2(acc[nt][0] + bv2.x, acc[nt][1] + bv2.y);
        float2 o1 = make_float2(acc[nt][2] + bv2.x, acc[nt][3] + bv2.y);
        *(float2*)(out + (size_t)r0 * DD + col) = o0;
        *(float2*)(out + (size_t)(r0 + 8) * DD + col) = o1;
    }
}

// ---------------------------------------------------------------------------
extern "C" void kernel_launch(void* const* d_in, const int* in_sizes, int n_in,
                              void* d_out, int out_size) {
    const float* frame = (const float*)d_in[0];   // [8, 8192, 512] f32
    const void*  bb    = d_in[1];                 // [8, 512, 2] int32 or int64
    const float* W     = (const float*)d_in[2];   // [544, 512] f32
    const float* bias  = (const float*)d_in[3];   // [512] f32
    float* out = (float*)d_out;                   // [8, 512, 512] f32

    k_combo1<<<NB_SUM + NB_WS + NB_F + NB_BND, 256>>>((const float4*)frame, W, bb);
    k_gscan<<<128, 256>>>();
    k_seg<<<BB * MM, 128>>>((const float4*)frame);
    dim3 g(NROWS / 64, DD / 128);
    k_gemm<<<g, 256>>>(bias, out);
}

// round 14
// speedup vs baseline: 4.0218x; 1.1260x over previous
#include <cuda_runtime.h>
#include <cuda_bf16.h>
#include <cstdint>

#define BB 8
#define TT 8192
#define DD 512
#define MM 512
#define KIN 544        // DD + 32 fourier dims
#define CH 8           // rows per chunk
#define NC 1024        // TT / CH chunks per batch
#define GRP 8          // chunks per group
#define NG 128         // groups per batch (NC / GRP)
#define D4 128         // DD / 4
#define NROWS (BB*MM)  // 4096 output rows
#define NKS 17         // k32-steps per product (544/32)
#define NIT 51         // 3 products x 17

// combo1 block ranges
#define NB_SUM 512     // sumpre: 2 groups per block
#define NB_WS  1088    // wsplit (KIN*DD/256)
#define NB_F   64      // fourier
#define NB_BND 16      // bounds (4096/256)

// Scratch (allocation-free rule: __device__ globals)
__device__ float g_cpre[BB * NC * DD];        // 16.8 MB within-group exclusive chunk prefix
__device__ float g_gtot[BB * NG * DD];        //  2.1 MB group totals
__device__ float g_gpre[BB * (NG + 1) * DD];  //  2.1 MB exclusive group prefix
__device__ __nv_bfloat16 g_Xhi[NROWS * KIN];  //  4.5 MB X split-high [row][k]
__device__ __nv_bfloat16 g_Xlo[NROWS * KIN];  //  4.5 MB X split-low
__device__ __nv_bfloat16 g_Whi[KIN * DD];     //  0.56 MB W split-high [k][n]
__device__ __nv_bfloat16 g_Wlo[KIN * DD];     //  0.56 MB W split-low
__device__ int2  g_se  [NROWS];               // clamped (s, e) per segment

__device__ __forceinline__ uint32_t smem_u32(const void* p) {
    uint32_t a;
    asm("{ .reg .u64 t; cvta.to.shared.u64 t, %1; cvt.u32.u64 %0, t; }" : "=r"(a) : "l"(p));
    return a;
}

// ---------------------------------------------------------------------------
// K_combo1: ONE launch for all independent front work (block-range dispatch):
//   [0, 512)        chunk sums + within-group prefix + group totals (2 grp/blk)
//   [512, 1600)     W f32 -> bf16 hi/lo split
//   [1600, 1664)    fourier features -> g_Xhi/g_Xlo cols 512..543
//   [1664, 1680)    bounds clamp, with per-block int64 self-detection
// ---------------------------------------------------------------------------
__global__ void __launch_bounds__(256) k_combo1(const float4* __restrict__ fr,
                                                const float* __restrict__ W,
                                                const void* __restrict__ bbv) {
    int bid = blockIdx.x, tid = threadIdx.x;

    if (bid < NB_SUM) {
        int b = bid >> 6;
        int g = (bid & 63) * 2 + (tid >> 7);
        int t = tid & 127;
        const float4* p = fr + (size_t)(b * TT + g * GRP * CH) * D4 + t;
        float4* cp = (float4*)g_cpre + (size_t)(b * NC + g * GRP) * D4 + t;

        float4 run = make_float4(0.f, 0.f, 0.f, 0.f);
#pragma unroll
        for (int c = 0; c < GRP; c++) {
            cp[(size_t)c * D4] = run;
            float4 s = make_float4(0.f, 0.f, 0.f, 0.f);
#pragma unroll
            for (int r = 0; r < CH; r++) {
                float4 v = p[(size_t)(c * CH + r) * D4];
                s.x += v.x; s.y += v.y; s.z += v.z; s.w += v.w;
            }
            run.x += s.x; run.y += s.y; run.z += s.z; run.w += s.w;
        }
        ((float4*)g_gtot)[(size_t)(b * NG + g) * D4 + t] = run;

    } else if (bid < NB_SUM + NB_WS) {
        int i = (bid - NB_SUM) * 256 + tid;
        float v = W[i];
        __nv_bfloat16 h = __float2bfloat16(v);
        g_Whi[i] = h;
        g_Wlo[i] = __float2bfloat16(v - __bfloat162float(h));

    } else if (bid < NB_SUM + NB_WS + NB_F) {
        int m = (bid - NB_SUM - NB_WS) * 8 + (tid >> 5);
        int i = tid & 31;
        const float pos = (float)m * (1.0f / 511.0f);
        const float step = (float)(6.907755278982137 / 15.0);  // log(1000)/15
        int fi = (i < 16) ? i : i - 16;
        float arg = (float)fi * step;
        float freq = (float)exp((double)arg);
        float ang = pos * freq;
        double angd = (double)ang;
        float v = (i < 16) ? (float)sin(angd) : (float)cos(angd);
        __nv_bfloat16 h = __float2bfloat16(v);
        __nv_bfloat16 l = __float2bfloat16(v - __bfloat162float(h));
#pragma unroll
        for (int b = 0; b < BB; b++) {
            size_t idx = (size_t)(b * MM + m) * KIN + DD + i;
            g_Xhi[idx] = h;
            g_Xlo[idx] = l;
        }

    } else {
        __shared__ int s_any;
        if (tid == 0) s_any = 0;
        __syncthreads();
        const unsigned int* bbw = (const unsigned int*)bbv;
        int bad = 0;
        for (int i = 2 * tid + 1; i < BB * MM * 2; i += 2 * 256)
            if (bbw[i] != 0u) bad = 1;
        if (bad) atomicOr(&s_any, 1);
        __syncthreads();
        int is64 = (s_any == 0);

        int bm = (bid - NB_SUM - NB_WS - NB_F) * 256 + tid;
        long long s_raw, e_raw;
        if (is64) {
            const long long* p = (const long long*)bbv;
            s_raw = p[2 * bm]; e_raw = p[2 * bm + 1];
        } else {
            const int* p = (const int*)bbv;
            s_raw = p[2 * bm]; e_raw = p[2 * bm + 1];
        }
        long long sl = s_raw; if (sl < 0) sl = 0; if (sl > TT - 1) sl = TT - 1;
        long long el = e_raw; if (el > TT) el = TT; if (el < sl + 1) el = sl + 1;
        g_se[bm] = make_int2((int)sl, (int)el);
    }
}

// ---------------------------------------------------------------------------
// K2: warp-parallel exclusive prefix over 128 group totals.
// ---------------------------------------------------------------------------
__global__ void __launch_bounds__(256) k_gscan() {
    int wid = threadIdx.x >> 5, l = threadIdx.x & 31;
    int b  = blockIdx.x >> 4;
    int c4 = (blockIdx.x & 15) * 8 + wid;
    const float4* gt = (const float4*)g_gtot + (size_t)b * NG * D4 + c4;
    float4* gp = (float4*)g_gpre + (size_t)b * (NG + 1) * D4 + c4;

    float4 v[4];
    float4 s = make_float4(0.f, 0.f, 0.f, 0.f);
#pragma unroll
    for (int j = 0; j < 4; j++) {
        v[j] = gt[(size_t)(4 * l + j) * D4];
        s.x += v[j].x; s.y += v[j].y; s.z += v[j].z; s.w += v[j].w;
    }
    float4 inc = s;
#pragma unroll
    for (int off = 1; off < 32; off <<= 1) {
        float ux = __shfl_up_sync(0xffffffffu, inc.x, off);
        float uy = __shfl_up_sync(0xffffffffu, inc.y, off);
        float uz = __shfl_up_sync(0xffffffffu, inc.z, off);
        float uw = __shfl_up_sync(0xffffffffu, inc.w, off);
        if (l >= off) { inc.x += ux; inc.y += uy; inc.z += uz; inc.w += uw; }
    }
    float4 run = make_float4(inc.x - s.x, inc.y - s.y, inc.z - s.z, inc.w - s.w);
#pragma unroll
    for (int j = 0; j < 4; j++) {
        gp[(size_t)(4 * l + j) * D4] = run;
        run.x += v[j].x; run.y += v[j].y; run.z += v[j].z; run.w += v[j].w;
    }
    if (l == 31) gp[(size_t)NG * D4] = run;
}

// ---------------------------------------------------------------------------
// K3: per-segment mean -> bf16 hi/lo into g_Xhi/g_Xlo cols 0..511.
// ---------------------------------------------------------------------------
__global__ void __launch_bounds__(128) k_seg(const float4* __restrict__ fr) {
    int bm = blockIdx.x;
    int b = bm >> 9;

    int2 se = g_se[bm];
    int s = se.x, e = se.y;
    int cs = s >> 3, ce = e >> 3;

    int t = threadIdx.x;
    const float4* CP = (const float4*)g_cpre + (size_t)b * NC * D4 + t;
    const float4* GP = (const float4*)g_gpre + (size_t)b * (NG + 1) * D4 + t;

    float4 a = GP[(size_t)(ce >> 3) * D4];
    float4 q = GP[(size_t)(cs >> 3) * D4];
    {
        float4 c1 = CP[(size_t)cs * D4];
        q.x += c1.x; q.y += c1.y; q.z += c1.z; q.w += c1.w;
        if (ce < NC) {
            float4 c2 = CP[(size_t)ce * D4];
            a.x += c2.x; a.y += c2.y; a.z += c2.z; a.w += c2.w;
        }
    }
    a.x -= q.x; a.y -= q.y; a.z -= q.z; a.w -= q.w;

    const float4* fb = fr + (size_t)b * TT * D4 + t;
    float4 ve[7], vs[7];
#pragma unroll
    for (int j = 0; j < 7; j++) {
        int r = ce * CH + j;
        ve[j] = make_float4(0.f, 0.f, 0.f, 0.f);
        if (r < e) ve[j] = fb[(size_t)r * D4];
    }
#pragma unroll
    for (int j = 0; j < 7; j++) {
        int r = cs * CH + j;
        vs[j] = make_float4(0.f, 0.f, 0.f, 0.f);
        if (r < s) vs[j] = fb[(size_t)r * D4];
    }
#pragma unroll
    for (int j = 0; j < 7; j++) {
        a.x += ve[j].x - vs[j].x;
        a.y += ve[j].y - vs[j].y;
        a.z += ve[j].z - vs[j].z;
        a.w += ve[j].w - vs[j].w;
    }
    float inv = 1.0f / (float)(e - s);
    a.x *= inv; a.y *= inv; a.z *= inv; a.w *= inv;

    __nv_bfloat162 h0, h1, l0, l1;
    h0.x = __float2bfloat16(a.x); h0.y = __float2bfloat16(a.y);
    h1.x = __float2bfloat16(a.z); h1.y = __float2bfloat16(a.w);
    l0.x = __float2bfloat16(a.x - __bfloat162float(h0.x));
    l0.y = __float2bfloat16(a.y - __bfloat162float(h0.y));
    l1.x = __float2bfloat16(a.z - __bfloat162float(h1.x));
    l1.y = __float2bfloat16(a.w - __bfloat162float(h1.y));
    size_t base = (size_t)bm * KIN + 4 * t;
    *(__nv_bfloat162*)(g_Xhi + base)     = h0;
    *(__nv_bfloat162*)(g_Xhi + base + 2) = h1;
    *(__nv_bfloat162*)(g_Xlo + base)     = l0;
    *(__nv_bfloat162*)(g_Xlo + base + 2) = l1;
}

// ---------------------------------------------------------------------------
// K4: split-bf16 mma.sync GEMM v3. Block 128x128, grid (32, 4) — FIXED from
// round 13's (64, 4) which drove rbase past NROWS (the illegal access).
// 8 warps as 4m x 2n, warp tile 32x64: per k16 each warp does 2 A-LDSM.x4 +
// 4 B-LDSM.x4.trans -> 16 MMAs with 64 independent accumulator chains.
// ---------------------------------------------------------------------------
__global__ void __launch_bounds__(256)
k_gemm(const float* __restrict__ bias, float* __restrict__ out) {
    __shared__ __align__(16) unsigned char As[2][128 * 80];   // [m128][k32] bf16, pitch 80 B
    __shared__ __align__(16) unsigned char Bs[2][32 * 272];   // [k32][n128] bf16, pitch 272 B

    int tid = threadIdx.x, wid = tid >> 5, l = tid & 31;
    int rbase = blockIdx.x * 128, cbase = blockIdx.y * 128;
    int mw = (wid & 3) * 32;      // warp m offset (32 rows)
    int nw = (wid >> 2) * 64;     // warp n offset (64 cols)

    int arow = tid >> 1;                 // 0..127
    int ak = (tid & 1) * 16;             // k element offset (16 bf16 = 32 B)
    int brow = tid >> 3;                 // 0..31
    int bn = (tid & 7) * 16;             // n element offset

    const __nv_bfloat16* AP[3] = {
        g_Xhi + (size_t)(rbase + arow) * KIN + ak,
        g_Xhi + (size_t)(rbase + arow) * KIN + ak,
        g_Xlo + (size_t)(rbase + arow) * KIN + ak};
    const __nv_bfloat16* BP[3] = {
        g_Whi + (size_t)brow * DD + cbase + bn,
        g_Wlo + (size_t)brow * DD + cbase + bn,
        g_Whi + (size_t)brow * DD + cbase + bn};

    uint32_t asb = smem_u32(As), bsb = smem_u32(Bs);
    uint32_t ald = asb + (mw + (l & 15)) * 80 + (l >> 4) * 16;
    uint32_t bg = l >> 3;
    uint32_t bld = bsb + (((bg & 1) * 8) + (l & 7)) * 272 + (nw + (bg >> 1) * 8) * 2;

    float acc[2][8][4];
#pragma unroll
    for (int mt = 0; mt < 2; mt++)
#pragma unroll
        for (int nt = 0; nt < 8; nt++)
#pragma unroll
            for (int j = 0; j < 4; j++) acc[mt][nt][j] = 0.f;

    uint4 av0 = *(const uint4*)AP[0];
    uint4 av1 = *(const uint4*)(AP[0] + 8);
    uint4 bv0 = *(const uint4*)BP[0];
    uint4 bv1 = *(const uint4*)(BP[0] + 8);
    *(uint4*)(As[0] + arow * 80 + (tid & 1) * 32)      = av0;
    *(uint4*)(As[0] + arow * 80 + (tid & 1) * 32 + 16) = av1;
    *(uint4*)(Bs[0] + brow * 272 + (tid & 7) * 32)      = bv0;
    *(uint4*)(Bs[0] + brow * 272 + (tid & 7) * 32 + 16) = bv1;
    __syncthreads();

    int p2 = 0, kt2 = 0;
    for (int it = 0; it < NIT; it++) {
        int cb = it & 1;
        if (it + 1 < NIT) {
            if (++kt2 == NKS) { kt2 = 0; p2++; }
            av0 = *(const uint4*)(AP[p2] + kt2 * 32);
            av1 = *(const uint4*)(AP[p2] + kt2 * 32 + 8);
            bv0 = *(const uint4*)(BP[p2] + (size_t)kt2 * 32 * DD);
            bv1 = *(const uint4*)(BP[p2] + (size_t)kt2 * 32 * DD + 8);
        }
        uint32_t ab = ald + cb * (128 * 80);
        uint32_t bb = bld + cb * (32 * 272);
#pragma unroll
        for (int kk = 0; kk < 2; kk++) {
            uint32_t a_f[2][4];
#pragma unroll
            for (int mt = 0; mt < 2; mt++)
                asm volatile("ldmatrix.sync.aligned.m8n8.x4.shared.b16 {%0,%1,%2,%3}, [%4];"
                             : "=r"(a_f[mt][0]), "=r"(a_f[mt][1]),
                               "=r"(a_f[mt][2]), "=r"(a_f[mt][3])
                             : "r"(ab + mt * 16 * 80 + kk * 32));
            uint32_t b_f[8][2];
#pragma unroll
            for (int pr = 0; pr < 4; pr++)
                asm volatile("ldmatrix.sync.aligned.m8n8.x4.trans.shared.b16 {%0,%1,%2,%3}, [%4];"
                             : "=r"(b_f[2 * pr][0]), "=r"(b_f[2 * pr][1]),
                               "=r"(b_f[2 * pr + 1][0]), "=r"(b_f[2 * pr + 1][1])
                             : "r"(bb + kk * (16 * 272) + pr * 32));
#pragma unroll
            for (int mt = 0; mt < 2; mt++)
#pragma unroll
                for (int nt = 0; nt < 8; nt++)
                    asm volatile(
                        "mma.sync.aligned.m16n8k16.row.col.f32.bf16.bf16.f32 "
                        "{%0,%1,%2,%3}, {%4,%5,%6,%7}, {%8,%9}, {%0,%1,%2,%3};"
                        : "+f"(acc[mt][nt][0]), "+f"(acc[mt][nt][1]),
                          "+f"(acc[mt][nt][2]), "+f"(acc[mt][nt][3])
                        : "r"(a_f[mt][0]), "r"(a_f[mt][1]), "r"(a_f[mt][2]), "r"(a_f[mt][3]),
                          "r"(b_f[nt][0]), "r"(b_f[nt][1]));
        }
        if (it + 1 < NIT) {
            int nb = cb ^ 1;
            *(uint4*)(As[nb] + arow * 80 + (tid & 1) * 32)      = av0;
            *(uint4*)(As[nb] + arow * 80 + (tid & 1) * 32 + 16) = av1;
            *(uint4*)(Bs[nb] + brow * 272 + (tid & 7) * 32)      = bv0;
            *(uint4*)(Bs[nb] + brow * 272 + (tid & 7) * 32 + 16) = bv1;
        }
        __syncthreads();
    }

    int g = l >> 2, tg = l & 3;
#pragma unroll
    for (int mt = 0; mt < 2; mt++) {
#pragma unroll
        for (int nt = 0; nt < 8; nt++) {
            int col = cbase + nw + nt * 8 + 2 * tg;
            float2 bv2 = *(const float2*)(bias + col);
            int r0 = rbase + mw + mt * 16 + g;
            float2 o0 = make_float2(acc[mt][nt][0] + bv2.x, acc[mt][nt][1] + bv2.y);
            float2 o1 = make_float2(acc[mt][nt][2] + bv2.x, acc[mt][nt][3] + bv2.y);
            *(float2*)(out + (size_t)r0 * DD + col) = o0;
            *(float2*)(out + (size_t)(r0 + 8) * DD + col) = o1;
        }
    }
}

// ---------------------------------------------------------------------------
extern "C" void kernel_launch(void* const* d_in, const int* in_sizes, int n_in,
                              void* d_out, int out_size) {
    const float* frame = (const float*)d_in[0];   // [8, 8192, 512] f32
    const void*  bb    = d_in[1];                 // [8, 512, 2] int32 or int64
    const float* W     = (const float*)d_in[2];   // [544, 512] f32
    const float* bias  = (const float*)d_in[3];   // [512] f32
    float* out = (float*)d_out;                   // [8, 512, 512] f32

    k_combo1<<<NB_SUM + NB_WS + NB_F + NB_BND, 256>>>((const float4*)frame, W, bb);
    k_gscan<<<128, 256>>>();
    k_seg<<<BB * MM, 128>>>((const float4*)frame);
    dim3 g(NROWS / 128, DD / 128);   // FIXED: 32x4 blocks for 128-row tiles
    k_gemm<<<g, 256>>>(bias, out);
}